// round 1
// baseline (speedup 1.0000x reference)
#include <cuda_runtime.h>
#include <math.h>

#define NSEQ 2048
#define DDIM 64
#define HHEADS 8
#define BHN 16          // B*H

// scratch: scores stored TRANSPOSED  [bh][m][n]  (m-major -> pass2 loads coalesced)
__device__ float g_scoresT[(size_t)BHN * NSEQ * NSEQ];
__device__ float g_ncinv[BHN * NSEQ];   // n_c[m]^{-1/2}

// ---------------------------------------------------------------------------
// Pass 1: per (bh, 128-m tile) loop over all n tiles:
//   qk = Q[n]·K[m]  (fp32 SIMT GEMM, 8x8 microtile)
//   s  = (1 + acos(clip(qk)))^-5   (masked -> g = 10000)
//   write scoresT[m][n], accumulate column sums -> ncinv = rsqrt
// ---------------------------------------------------------------------------
__global__ __launch_bounds__(256, 1)
void spop_pass1(const float* __restrict__ Q,
                const float* __restrict__ K,
                const int*   __restrict__ mask)
{
    extern __shared__ float smem[];
    float4* Ks4  = (float4*)smem;              // 128 * 17 float4
    float4* Qs4  = Ks4 + 128 * 17;             // 128 * 17 float4
    float*  red  = (float*)(Qs4 + 128 * 17);   // 16 * 128 floats
    int*    mflg = (int*)(red + 16 * 128);     // 128 ints

    const int bh  = blockIdx.y;
    const int b   = bh / HHEADS;
    const int m0  = blockIdx.x * 128;
    const int tid = threadIdx.x;
    const int tx  = tid & 15;     // m groups (interleaved: m = tx + 16*j)
    const int ty  = tid >> 4;     // n groups (n = ty*8 + i)

    // load K tile (128 x 64 floats) with pad-17 float4 rows
    {
        const float4* Kg = (const float4*)(K + ((size_t)bh * NSEQ + m0) * DDIM);
        #pragma unroll
        for (int r = 0; r < 8; r++) {
            int idx = tid + 256 * r;
            int row = idx >> 4, c = idx & 15;
            Ks4[row * 17 + c] = Kg[row * 16 + c];
        }
    }
    if (tid < 128) mflg[tid] = mask[b * NSEQ + m0 + tid];

    float colacc[8];
    #pragma unroll
    for (int j = 0; j < 8; j++) colacc[j] = 0.0f;

    const float CLIPV = 1.0f - 1e-7f;

    for (int n0 = 0; n0 < NSEQ; n0 += 128) {
        __syncthreads();
        {
            const float4* Qg = (const float4*)(Q + ((size_t)bh * NSEQ + n0) * DDIM);
            #pragma unroll
            for (int r = 0; r < 8; r++) {
                int idx = tid + 256 * r;
                int row = idx >> 4, c = idx & 15;
                Qs4[row * 17 + c] = Qg[row * 16 + c];
            }
        }
        __syncthreads();

        float acc[8][8];
        #pragma unroll
        for (int i = 0; i < 8; i++)
            #pragma unroll
            for (int j = 0; j < 8; j++) acc[i][j] = 0.0f;

        #pragma unroll 4
        for (int kk = 0; kk < 16; kk++) {
            float4 a[8], bv[8];
            #pragma unroll
            for (int i = 0; i < 8; i++) a[i]  = Qs4[(ty * 8 + i) * 17 + kk];
            #pragma unroll
            for (int j = 0; j < 8; j++) bv[j] = Ks4[(tx + 16 * j) * 17 + kk];
            #pragma unroll
            for (int i = 0; i < 8; i++)
                #pragma unroll
                for (int j = 0; j < 8; j++) {
                    acc[i][j] += a[i].x * bv[j].x;
                    acc[i][j] += a[i].y * bv[j].y;
                    acc[i][j] += a[i].z * bv[j].z;
                    acc[i][j] += a[i].w * bv[j].w;
                }
        }

        // transform to scores, write transposed, accumulate column sums
        const int nbase = n0 + ty * 8;
        #pragma unroll
        for (int j = 0; j < 8; j++) {
            const int mloc = tx + 16 * j;
            const bool msk = (mflg[mloc] == 0);
            float s[8];
            #pragma unroll
            for (int i = 0; i < 8; i++) {
                float qk = acc[i][j];
                qk = fminf(fmaxf(qk, -CLIPV), CLIPV);
                float g  = msk ? 10000.0f : acosf(qk);
                float t  = 1.0f + g;
                float t2 = t * t;
                float t4 = t2 * t2;
                float sv = 1.0f / (t4 * t);   // t^-5
                s[i] = sv;
                colacc[j] += sv;
            }
            float4* dst = (float4*)(g_scoresT
                          + ((size_t)bh * NSEQ + (m0 + mloc)) * NSEQ + nbase);
            dst[0] = make_float4(s[0], s[1], s[2], s[3]);
            dst[1] = make_float4(s[4], s[5], s[6], s[7]);
        }
    }

    // reduce column sums over ty and store rsqrt
    __syncthreads();
    #pragma unroll
    for (int j = 0; j < 8; j++) red[ty * 128 + tx + 16 * j] = colacc[j];
    __syncthreads();
    if (tid < 128) {
        float ssum = 0.0f;
        #pragma unroll
        for (int r = 0; r < 16; r++) ssum += red[r * 128 + tid];
        g_ncinv[bh * NSEQ + m0 + tid] = rsqrtf(ssum);
    }
}

// ---------------------------------------------------------------------------
// Pass 2: per (bh, 128-n tile): out[n,:] = (sum_m w*V[m,:]) / (sum_m w),
//   w[n,m] = scoresT[m][n] * ncinv[m].  W (128x128) x V (128x64) fp32 GEMM
//   with fused row sums.
// ---------------------------------------------------------------------------
__global__ __launch_bounds__(256, 1)
void spop_pass2(const float* __restrict__ V,
                float*       __restrict__ out)
{
    extern __shared__ float smem[];
    float4* Ws4 = (float4*)smem;              // 128 rows * 33 float4 (pad)
    float4* Vs4 = Ws4 + 128 * 33;             // 128 rows * 17 float4 (pad)
    float*  rs  = (float*)(Vs4 + 128 * 17);   // 128 row sums

    const int bh  = blockIdx.y;
    const int n0  = blockIdx.x * 128;
    const int tid = threadIdx.x;
    const int tx  = tid & 15;     // d cols: d = tx*4 .. tx*4+3
    const int ty  = tid >> 4;     // n rows: n = ty*8 + i

    float acc[8][4];
    float rowacc[8];
    #pragma unroll
    for (int i = 0; i < 8; i++) {
        rowacc[i] = 0.0f;
        #pragma unroll
        for (int c = 0; c < 4; c++) acc[i][c] = 0.0f;
    }

    for (int m0 = 0; m0 < NSEQ; m0 += 128) {
        __syncthreads();
        // V tile
        {
            const float4* Vg = (const float4*)(V + ((size_t)bh * NSEQ + m0) * DDIM);
            #pragma unroll
            for (int r = 0; r < 8; r++) {
                int idx = tid + 256 * r;
                int row = idx >> 4, c = idx & 15;
                Vs4[row * 17 + c] = Vg[row * 16 + c];
            }
        }
        // W tile: scoresT rows m0..m0+127, cols n0..n0+127, scaled by ncinv[m]
        {
            const float4* Wg = (const float4*)(g_scoresT
                               + ((size_t)bh * NSEQ + m0) * NSEQ + n0);
            #pragma unroll
            for (int r = 0; r < 16; r++) {
                int idx = tid + 256 * r;
                int row = idx >> 5, c = idx & 31;
                float nci = g_ncinv[bh * NSEQ + m0 + row];
                float4 w = Wg[(size_t)row * (NSEQ / 4) + c];
                w.x *= nci; w.y *= nci; w.z *= nci; w.w *= nci;
                Ws4[row * 33 + c] = w;
            }
        }
        __syncthreads();

        #pragma unroll 4
        for (int m = 0; m < 128; m++) {
            float4 v   = Vs4[m * 17 + tx];
            float4 wlo = Ws4[m * 33 + ty * 2];
            float4 whi = Ws4[m * 33 + ty * 2 + 1];
            float w[8] = {wlo.x, wlo.y, wlo.z, wlo.w, whi.x, whi.y, whi.z, whi.w};
            #pragma unroll
            for (int i = 0; i < 8; i++) {
                acc[i][0] += w[i] * v.x;
                acc[i][1] += w[i] * v.y;
                acc[i][2] += w[i] * v.z;
                acc[i][3] += w[i] * v.w;
            }
            if (tx == 0) {
                #pragma unroll
                for (int i = 0; i < 8; i++) rowacc[i] += w[i];
            }
        }
    }

    __syncthreads();
    if (tx == 0) {
        #pragma unroll
        for (int i = 0; i < 8; i++) rs[ty * 8 + i] = rowacc[i];
    }
    __syncthreads();

    float4* Og = (float4*)(out + ((size_t)bh * NSEQ + n0) * DDIM);
    #pragma unroll
    for (int i = 0; i < 8; i++) {
        int nloc = ty * 8 + i;
        float inv = 1.0f / rs[nloc];
        Og[nloc * 16 + tx] = make_float4(acc[i][0] * inv, acc[i][1] * inv,
                                         acc[i][2] * inv, acc[i][3] * inv);
    }
}

// ---------------------------------------------------------------------------

extern "C" void kernel_launch(void* const* d_in, const int* in_sizes, int n_in,
                              void* d_out, int out_size)
{
    const float* Q    = (const float*)d_in[0];
    const float* K    = (const float*)d_in[1];
    const float* V    = (const float*)d_in[2];
    const int*   mask = (const int*)d_in[3];
    float*       out  = (float*)d_out;

    const int SMEM1 = (128 * 17 * 16) * 2 + 16 * 128 * 4 + 128 * 4;   // 78336
    const int SMEM2 = 128 * 33 * 16 + 128 * 17 * 16 + 128 * 4;        // 102912

    cudaFuncSetAttribute(spop_pass1, cudaFuncAttributeMaxDynamicSharedMemorySize, SMEM1);
    cudaFuncSetAttribute(spop_pass2, cudaFuncAttributeMaxDynamicSharedMemorySize, SMEM2);

    dim3 grid(NSEQ / 128, BHN);   // (16, 16)
    spop_pass1<<<grid, 256, SMEM1>>>(Q, K, mask);
    spop_pass2<<<grid, 256, SMEM2>>>(V, out);
}

// round 3
// speedup vs baseline: 1.3635x; 1.3635x over previous
#include <cuda_runtime.h>
#include <cuda_bf16.h>
#include <math.h>
#include <cstdint>

#define NSEQ 2048
#define DDIM 64
#define HHEADS 8
#define BHN 16

__device__ float g_scoresT[(size_t)BHN * NSEQ * NSEQ];   // [bh][m][n]
__device__ float g_ncinv[BHN * NSEQ];

// ---------------------------------------------------------------------------
__device__ __forceinline__ uint32_t smem_u32(const void* p) {
    uint32_t a;
    asm("{ .reg .u64 t; cvta.to.shared.u64 t, %1; cvt.u32.u64 %0, t; }"
        : "=r"(a) : "l"(p));
    return a;
}
__device__ __forceinline__ void ldsm_x4(uint32_t r[4], uint32_t a) {
    asm volatile("ldmatrix.sync.aligned.m8n8.x4.shared.b16 {%0,%1,%2,%3}, [%4];"
        : "=r"(r[0]), "=r"(r[1]), "=r"(r[2]), "=r"(r[3]) : "r"(a));
}
__device__ __forceinline__ void ldsm_x4_t(uint32_t r[4], uint32_t a) {
    asm volatile("ldmatrix.sync.aligned.m8n8.x4.trans.shared.b16 {%0,%1,%2,%3}, [%4];"
        : "=r"(r[0]), "=r"(r[1]), "=r"(r[2]), "=r"(r[3]) : "r"(a));
}
__device__ __forceinline__ void ldsm_x2_t(uint32_t r[2], uint32_t a) {
    asm volatile("ldmatrix.sync.aligned.m8n8.x2.trans.shared.b16 {%0,%1}, [%2];"
        : "=r"(r[0]), "=r"(r[1]) : "r"(a));
}
__device__ __forceinline__ void mma_bf16(float c[4], const uint32_t a[4],
                                         uint32_t b0, uint32_t b1) {
    asm volatile("mma.sync.aligned.m16n8k16.row.col.f32.bf16.bf16.f32 "
        "{%0,%1,%2,%3}, {%4,%5,%6,%7}, {%8,%9}, {%0,%1,%2,%3};"
        : "+f"(c[0]), "+f"(c[1]), "+f"(c[2]), "+f"(c[3])
        : "r"(a[0]), "r"(a[1]), "r"(a[2]), "r"(a[3]), "r"(b0), "r"(b1));
}

#define SWZ128(o) ((o) ^ (((o) >> 3) & 0x70))
#define SWZ256(o) ((o) ^ (((o) >> 4) & 0x70))

__device__ __forceinline__ uint32_t bfu(__nv_bfloat16 h) {
    return (uint32_t)__bfloat16_as_ushort(h);
}
// split 8 consecutive floats into hi/lo bf16 16B units
__device__ __forceinline__ void split8(const float* f, uint4& H, uint4& L) {
    uint32_t h[4], l[4];
    #pragma unroll
    for (int p = 0; p < 4; p++) {
        float x0 = f[2*p], x1 = f[2*p+1];
        __nv_bfloat16 h0 = __float2bfloat16(x0);
        __nv_bfloat16 h1 = __float2bfloat16(x1);
        h[p] = bfu(h0) | (bfu(h1) << 16);
        float r0 = x0 - __bfloat162float(h0);
        float r1 = x1 - __bfloat162float(h1);
        l[p] = bfu(__float2bfloat16(r0)) | (bfu(__float2bfloat16(r1)) << 16);
    }
    H = make_uint4(h[0], h[1], h[2], h[3]);
    L = make_uint4(l[0], l[1], l[2], l[3]);
}

__device__ __forceinline__ float score_fn(float qk, bool msk) {
    const float CLIPV = 1.0f - 1e-7f;
    qk = fminf(fmaxf(qk, -CLIPV), CLIPV);
    float gd = msk ? 10000.0f : acosf(qk);
    float t = 1.0f + gd;
    float t2 = t * t;
    return __fdividef(1.0f, t2 * t2 * t);
}

// smem offsets pass1
#define P1_KH 0
#define P1_KL 16384
#define P1_QH 32768
#define P1_QL 49152
#define P1_RED 65536
#define P1_SMEM (65536 + 1024)

// ---------------------------------------------------------------------------
// Pass 1: qk = K[m,:]·Q[n,:]  via HMMA bf16x2-split (terms hh, lh, hl)
// ---------------------------------------------------------------------------
__global__ __launch_bounds__(256, 1)
void spop_pass1_mma(const float* __restrict__ Q,
                    const float* __restrict__ K,
                    const int*   __restrict__ mask)
{
    extern __shared__ char sm[];
    const uint32_t sb = smem_u32(sm);

    const int bh = blockIdx.y;
    const int b  = bh / HHEADS;
    const int m0 = blockIdx.x * 128;
    const int tid = threadIdx.x;
    const int lane = tid & 31;
    const int wid  = tid >> 5;
    const int wm = wid & 3;        // m quarter (32 rows)
    const int wn = wid >> 2;       // n half (64 cols)
    const int g   = lane >> 2;     // row group
    const int tig = lane & 3;

    // ---- K tile split -> smem ----
    {
        const int r = tid >> 1, half = tid & 1;
        const float* Kg = K + ((size_t)bh * NSEQ + m0 + r) * DDIM + half * 32;
        float f[32];
        #pragma unroll
        for (int i = 0; i < 8; i++) {
            float4 v = ((const float4*)Kg)[i];
            f[4*i] = v.x; f[4*i+1] = v.y; f[4*i+2] = v.z; f[4*i+3] = v.w;
        }
        #pragma unroll
        for (int u = 0; u < 4; u++) {
            uint4 H, L;
            split8(f + 8*u, H, L);
            uint32_t off = SWZ128((uint32_t)(r * 128 + half * 64 + u * 16));
            *(uint4*)(sm + P1_KH + off) = H;
            *(uint4*)(sm + P1_KL + off) = L;
        }
    }

    // mask flags for this lane's 4 m rows: wm*32 + {g, g+8, 16+g, 24+g}
    bool mskf[4];
    #pragma unroll
    for (int q = 0; q < 4; q++) {
        int mloc = wm * 32 + (q >> 1) * 16 + (q & 1) * 8 + g;
        mskf[q] = (mask[b * NSEQ + m0 + mloc] == 0);
    }

    float rowacc[4] = {0.f, 0.f, 0.f, 0.f};

    // per-lane ldmatrix address components
    const uint32_t a_row = (uint32_t)(wm * 32 + (lane & 15));
    const uint32_t a_k16 = (uint32_t)((lane >> 4) * 16);          // bytes
    const uint32_t b_row = (uint32_t)(wn * 64 + ((lane >> 3) & 1) * 8 + (lane & 7));
    const uint32_t b_k16 = (uint32_t)((lane >> 4) * 16);

    for (int it = 0; it < NSEQ / 128; it++) {
        const int n0 = it * 128;
        __syncthreads();     // previous iter's smem reads done

        // ---- Q tile split -> smem ----
        {
            const int r = tid >> 1, half = tid & 1;
            const float* Qg = Q + ((size_t)bh * NSEQ + n0 + r) * DDIM + half * 32;
            float f[32];
            #pragma unroll
            for (int i = 0; i < 8; i++) {
                float4 v = ((const float4*)Qg)[i];
                f[4*i] = v.x; f[4*i+1] = v.y; f[4*i+2] = v.z; f[4*i+3] = v.w;
            }
            #pragma unroll
            for (int u = 0; u < 4; u++) {
                uint4 H, L;
                split8(f + 8*u, H, L);
                uint32_t off = SWZ128((uint32_t)(r * 128 + half * 64 + u * 16));
                *(uint4*)(sm + P1_QH + off) = H;
                *(uint4*)(sm + P1_QL + off) = L;
            }
        }
        __syncthreads();

        float acc[2][8][4];
        #pragma unroll
        for (int tm = 0; tm < 2; tm++)
            #pragma unroll
            for (int tn = 0; tn < 8; tn++)
                #pragma unroll
                for (int c = 0; c < 4; c++) acc[tm][tn][c] = 0.f;

        #pragma unroll
        for (int kc = 0; kc < 4; kc++) {
            uint32_t Ah[2][4], Al[2][4], Bq[4][4];
            const uint32_t kb = (uint32_t)(kc * 32) + a_k16;
            #pragma unroll
            for (int tm = 0; tm < 2; tm++)
                ldsm_x4(Ah[tm], sb + P1_KH + SWZ128((a_row + tm*16) * 128 + kb));
            #pragma unroll
            for (int p = 0; p < 4; p++)
                ldsm_x4(Bq[p], sb + P1_QH + SWZ128((b_row + p*16) * 128 + (uint32_t)(kc*32) + b_k16));
            // hh
            #pragma unroll
            for (int tm = 0; tm < 2; tm++)
                #pragma unroll
                for (int tn = 0; tn < 8; tn++)
                    mma_bf16(acc[tm][tn], Ah[tm],
                             Bq[tn>>1][(tn&1)], Bq[tn>>1][2 + (tn&1)]);
            // lh (Al * Bh)
            #pragma unroll
            for (int tm = 0; tm < 2; tm++)
                ldsm_x4(Al[tm], sb + P1_KL + SWZ128((a_row + tm*16) * 128 + kb));
            #pragma unroll
            for (int tm = 0; tm < 2; tm++)
                #pragma unroll
                for (int tn = 0; tn < 8; tn++)
                    mma_bf16(acc[tm][tn], Al[tm],
                             Bq[tn>>1][(tn&1)], Bq[tn>>1][2 + (tn&1)]);
            // hl (Ah * Bl) — reload B from lo plane
            #pragma unroll
            for (int p = 0; p < 4; p++)
                ldsm_x4(Bq[p], sb + P1_QL + SWZ128((b_row + p*16) * 128 + (uint32_t)(kc*32) + b_k16));
            #pragma unroll
            for (int tm = 0; tm < 2; tm++)
                #pragma unroll
                for (int tn = 0; tn < 8; tn++)
                    mma_bf16(acc[tm][tn], Ah[tm],
                             Bq[tn>>1][(tn&1)], Bq[tn>>1][2 + (tn&1)]);
        }

        // ---- epilogue: transform + store + column sums ----
        #pragma unroll
        for (int tm = 0; tm < 2; tm++) {
            #pragma unroll
            for (int h = 0; h < 2; h++) {
                const int q = tm * 2 + h;
                const int mloc = wm * 32 + tm * 16 + h * 8 + g;
                const bool mk = mskf[q];
                float* dst = g_scoresT + ((size_t)bh * NSEQ + m0 + mloc) * NSEQ
                             + n0 + wn * 64 + 2 * tig;
                float racc = 0.f;
                #pragma unroll
                for (int tn = 0; tn < 8; tn++) {
                    float s0 = score_fn(acc[tm][tn][2*h],     mk);
                    float s1 = score_fn(acc[tm][tn][2*h + 1], mk);
                    racc += s0 + s1;
                    *(float2*)(dst + tn * 8) = make_float2(s0, s1);
                }
                rowacc[q] += racc;
            }
        }
    }

    // reduce across the 4 lanes of each row group
    #pragma unroll
    for (int q = 0; q < 4; q++) {
        rowacc[q] += __shfl_xor_sync(0xffffffffu, rowacc[q], 1);
        rowacc[q] += __shfl_xor_sync(0xffffffffu, rowacc[q], 2);
    }
    float* red = (float*)(sm + P1_RED);
    if (tig == 0) {
        #pragma unroll
        for (int q = 0; q < 4; q++) {
            int mloc = wm * 32 + (q >> 1) * 16 + (q & 1) * 8 + g;
            red[wn * 128 + mloc] = rowacc[q];
        }
    }
    __syncthreads();
    if (tid < 128)
        g_ncinv[bh * NSEQ + m0 + tid] = rsqrtf(red[tid] + red[128 + tid]);
}

// smem offsets pass2
#define P2_WH 0
#define P2_WL 32768
#define P2_VH 65536
#define P2_VL 83968
#define P2_SMEM 102400
#define VSTRIDE 144   // bytes per V smem row (72 bf16)

// ---------------------------------------------------------------------------
// Pass 2: out[n,:] = (sum_m w V) / (sum_m w),  w = scoresT[m][n]*ncinv[m]
//   A = W (n x m) via trans-ldmatrix from [m][n] planes
//   B = V (m x 72), col 64 = ones (row sums for free)
// ---------------------------------------------------------------------------
__global__ __launch_bounds__(256, 1)
void spop_pass2_mma(const float* __restrict__ V,
                    float*       __restrict__ out)
{
    extern __shared__ char sm[];
    const uint32_t sb = smem_u32(sm);

    const int bh = blockIdx.y;
    const int n0 = blockIdx.x * 128;
    const int tid = threadIdx.x;
    const int lane = tid & 31;
    const int wid  = tid >> 5;
    const int wn = wid & 3;        // n quarter within tile? -> 8 warps: 4 x n, 2 x ... 
    const int wq = wid >> 2;       // splits the m-k work? no: use 8 warps over n: 8*16=128? 
    // Layout: 8 warps, each owns 16 n rows? Use warp n-tile of 32 rows x 72 d:
    // warps 0..3 -> n quarters, warps 4..7 -> same quarters, second half? 
    // Simpler: 8 warps each own 16 n-rows (1 m16 tile) x 72 d.
    const int wrow = wid * 16;     // n rows [wrow, wrow+16)

    float acc[9][4];
    #pragma unroll
    for (int dt = 0; dt < 9; dt++)
        #pragma unroll
        for (int c = 0; c < 4; c++) acc[dt][c] = 0.f;

    const int g = lane >> 2, tig = lane & 3;

    // per-lane address components
    const uint32_t a_min  = (uint32_t)((lane & 7) + ((lane >> 4) & 1) * 8);  // m row in 16
    const uint32_t a_noff = (uint32_t)(((lane >> 3) & 1) * 8);               // n offset
    const uint32_t b_kin  = (uint32_t)((lane & 7) + ((lane >> 3) & 1) * 8);  // k row in 16
    const uint32_t b_doff = (uint32_t)((lane >> 4) * 8);                     // d offset
    const uint32_t b_kin2 = (uint32_t)(lane & 15);                           // for x2

    for (int m0 = 0; m0 < NSEQ; m0 += 128) {
        __syncthreads();
        // ---- W chunk: load scoresT, scale by ncinv, split -> WH/WL ----
        {
            const int r = tid >> 1, half = tid & 1;
            const float nci = g_ncinv[bh * NSEQ + m0 + r];
            const float* Wg = g_scoresT + ((size_t)bh * NSEQ + m0 + r) * NSEQ
                              + n0 + half * 64;
            #pragma unroll
            for (int u = 0; u < 8; u++) {
                float4 v0 = ((const float4*)Wg)[2*u];
                float4 v1 = ((const float4*)Wg)[2*u+1];
                float f[8] = {v0.x*nci, v0.y*nci, v0.z*nci, v0.w*nci,
                              v1.x*nci, v1.y*nci, v1.z*nci, v1.w*nci};
                uint4 H, L;
                split8(f, H, L);
                uint32_t off = SWZ256((uint32_t)(r * 256 + half * 128 + u * 16));
                *(uint4*)(sm + P2_WH + off) = H;
                *(uint4*)(sm + P2_WL + off) = L;
            }
        }
        // ---- V chunk split -> VH/VL (+ ones col 64) ----
        {
            const int r = tid >> 1, half = tid & 1;
            const float* Vg = V + ((size_t)bh * NSEQ + m0 + r) * DDIM + half * 32;
            float f[32];
            #pragma unroll
            for (int i = 0; i < 8; i++) {
                float4 v = ((const float4*)Vg)[i];
                f[4*i] = v.x; f[4*i+1] = v.y; f[4*i+2] = v.z; f[4*i+3] = v.w;
            }
            #pragma unroll
            for (int u = 0; u < 4; u++) {
                uint4 H, L;
                split8(f + 8*u, H, L);
                uint32_t off = (uint32_t)(r * VSTRIDE + half * 64 + u * 16);
                *(uint4*)(sm + P2_VH + off) = H;
                *(uint4*)(sm + P2_VL + off) = L;
            }
            if (half == 1) {
                uint32_t off = (uint32_t)(r * VSTRIDE + 128);
                *(uint4*)(sm + P2_VH + off) = make_uint4(0x00003F80u, 0u, 0u, 0u);
                *(uint4*)(sm + P2_VL + off) = make_uint4(0u, 0u, 0u, 0u);
            }
        }
        __syncthreads();

        #pragma unroll
        for (int kc = 0; kc < 8; kc++) {
            uint32_t Awh[4], Awl[4], Bv[4][4], Bv8[2];
            const uint32_t mbyte = ((uint32_t)(kc * 16) + a_min) * 256;
            const uint32_t nbyte = ((uint32_t)wrow + a_noff) * 2;
            ldsm_x4_t(Awh, sb + P2_WH + SWZ256(mbyte + nbyte));
            // B hi
            #pragma unroll
            for (int p = 0; p < 4; p++)
                ldsm_x4_t(Bv[p], sb + P2_VH + ((uint32_t)(kc*16) + b_kin) * VSTRIDE
                                + (uint32_t)(p * 32) + b_doff * 2);
            ldsm_x2_t(Bv8, sb + P2_VH + ((uint32_t)(kc*16) + b_kin2) * VSTRIDE + 128);
            // wh * vh (9 tiles)
            #pragma unroll
            for (int dt = 0; dt < 8; dt++)
                mma_bf16(acc[dt], Awh, Bv[dt>>1][(dt&1)*2], Bv[dt>>1][(dt&1)*2+1]);
            mma_bf16(acc[8], Awh, Bv8[0], Bv8[1]);
            // wl * vh (9 tiles)
            ldsm_x4_t(Awl, sb + P2_WL + SWZ256(mbyte + nbyte));
            #pragma unroll
            for (int dt = 0; dt < 8; dt++)
                mma_bf16(acc[dt], Awl, Bv[dt>>1][(dt&1)*2], Bv[dt>>1][(dt&1)*2+1]);
            mma_bf16(acc[8], Awl, Bv8[0], Bv8[1]);
            // wh * vl (8 tiles, ones col is zero in lo plane)
            #pragma unroll
            for (int p = 0; p < 4; p++)
                ldsm_x4_t(Bv[p], sb + P2_VL + ((uint32_t)(kc*16) + b_kin) * VSTRIDE
                                + (uint32_t)(p * 32) + b_doff * 2);
            #pragma unroll
            for (int dt = 0; dt < 8; dt++)
                mma_bf16(acc[dt], Awh, Bv[dt>>1][(dt&1)*2], Bv[dt>>1][(dt&1)*2+1]);
        }
    }

    // ---- epilogue: divide by row sum (col 64), store ----
    const int srcl = lane & ~3;
    float sum0 = __shfl_sync(0xffffffffu, acc[8][0], srcl);
    float sum1 = __shfl_sync(0xffffffffu, acc[8][2], srcl);
    float inv0 = __fdividef(1.0f, sum0);
    float inv1 = __fdividef(1.0f, sum1);

    const int ng0 = n0 + wrow + g;
    float* O0 = out + ((size_t)bh * NSEQ + ng0) * DDIM + 2 * tig;
    float* O1 = out + ((size_t)bh * NSEQ + ng0 + 8) * DDIM + 2 * tig;
    #pragma unroll
    for (int dt = 0; dt < 8; dt++) {
        *(float2*)(O0 + dt * 8) = make_float2(acc[dt][0] * inv0, acc[dt][1] * inv0);
        *(float2*)(O1 + dt * 8) = make_float2(acc[dt][2] * inv1, acc[dt][3] * inv1);
    }
}

// ---------------------------------------------------------------------------
extern "C" void kernel_launch(void* const* d_in, const int* in_sizes, int n_in,
                              void* d_out, int out_size)
{
    const float* Q    = (const float*)d_in[0];
    const float* K    = (const float*)d_in[1];
    const float* V    = (const float*)d_in[2];
    const int*   mask = (const int*)d_in[3];
    float*       out  = (float*)d_out;

    cudaFuncSetAttribute(spop_pass1_mma, cudaFuncAttributeMaxDynamicSharedMemorySize, P1_SMEM);
    cudaFuncSetAttribute(spop_pass2_mma, cudaFuncAttributeMaxDynamicSharedMemorySize, P2_SMEM);

    dim3 grid(NSEQ / 128, BHN);   // (16, 16)
    spop_pass1_mma<<<grid, 256, P1_SMEM>>>(Q, K, mask);
    spop_pass2_mma<<<grid, 256, P2_SMEM>>>(V, out);
}

// round 4
// speedup vs baseline: 1.7280x; 1.2673x over previous
#include <cuda_runtime.h>
#include <cuda_bf16.h>
#include <math.h>
#include <cstdint>

#define NSEQ 2048
#define DDIM 64
#define HHEADS 8
#define BHN 16

#define QK_ELEMS ((size_t)BHN * NSEQ * DDIM)    // 2,097,152
#define S_ELEMS  ((size_t)BHN * NSEQ * NSEQ)    // 67,108,864

// pre-split bf16 hi/lo planes (uint4 for 16B alignment)
__device__ uint4 g_qh4[QK_ELEMS / 8], g_ql4[QK_ELEMS / 8];
__device__ uint4 g_kh4[QK_ELEMS / 8], g_kl4[QK_ELEMS / 8];
// scores planes [bh][m][n] bf16 hi/lo
__device__ uint4 g_sH4[S_ELEMS / 8], g_sL4[S_ELEMS / 8];
__device__ float g_ncinv[BHN * NSEQ];

// ---------------------------------------------------------------------------
__device__ __forceinline__ uint32_t smem_u32(const void* p) {
    uint32_t a;
    asm("{ .reg .u64 t; cvta.to.shared.u64 t, %1; cvt.u32.u64 %0, t; }"
        : "=r"(a) : "l"(p));
    return a;
}
__device__ __forceinline__ void ldsm_x4(uint32_t r[4], uint32_t a) {
    asm volatile("ldmatrix.sync.aligned.m8n8.x4.shared.b16 {%0,%1,%2,%3}, [%4];"
        : "=r"(r[0]), "=r"(r[1]), "=r"(r[2]), "=r"(r[3]) : "r"(a));
}
__device__ __forceinline__ void ldsm_x4_t(uint32_t r[4], uint32_t a) {
    asm volatile("ldmatrix.sync.aligned.m8n8.x4.trans.shared.b16 {%0,%1,%2,%3}, [%4];"
        : "=r"(r[0]), "=r"(r[1]), "=r"(r[2]), "=r"(r[3]) : "r"(a));
}
__device__ __forceinline__ void ldsm_x2_t(uint32_t r[2], uint32_t a) {
    asm volatile("ldmatrix.sync.aligned.m8n8.x2.trans.shared.b16 {%0,%1}, [%2];"
        : "=r"(r[0]), "=r"(r[1]) : "r"(a));
}
__device__ __forceinline__ void mma_bf16(float c[4], const uint32_t a[4],
                                         uint32_t b0, uint32_t b1) {
    asm volatile("mma.sync.aligned.m16n8k16.row.col.f32.bf16.bf16.f32 "
        "{%0,%1,%2,%3}, {%4,%5,%6,%7}, {%8,%9}, {%0,%1,%2,%3};"
        : "+f"(c[0]), "+f"(c[1]), "+f"(c[2]), "+f"(c[3])
        : "r"(a[0]), "r"(a[1]), "r"(a[2]), "r"(a[3]), "r"(b0), "r"(b1));
}
__device__ __forceinline__ void cp16(uint32_t dst, const void* src) {
    asm volatile("cp.async.cg.shared.global [%0], [%1], 16;"
        :: "r"(dst), "l"(src) : "memory");
}
#define CP_COMMIT() asm volatile("cp.async.commit_group;" ::: "memory")
#define CP_WAIT0()  asm volatile("cp.async.wait_group 0;" ::: "memory")

#define SWZ128(o) ((o) ^ (((o) >> 3) & 0x70))
#define SWZ256(o) ((o) ^ (((o) >> 4) & 0x70))

__device__ __forceinline__ uint32_t bfu(__nv_bfloat16 h) {
    return (uint32_t)__bfloat16_as_ushort(h);
}
__device__ __forceinline__ void split8(const float* f, uint4& H, uint4& L) {
    uint32_t h[4], l[4];
    #pragma unroll
    for (int p = 0; p < 4; p++) {
        float x0 = f[2*p], x1 = f[2*p+1];
        __nv_bfloat16 h0 = __float2bfloat16(x0);
        __nv_bfloat16 h1 = __float2bfloat16(x1);
        h[p] = bfu(h0) | (bfu(h1) << 16);
        float r0 = x0 - __bfloat162float(h0);
        float r1 = x1 - __bfloat162float(h1);
        l[p] = bfu(__float2bfloat16(r0)) | (bfu(__float2bfloat16(r1)) << 16);
    }
    H = make_uint4(h[0], h[1], h[2], h[3]);
    L = make_uint4(l[0], l[1], l[2], l[3]);
}

__device__ __forceinline__ float score_fn(float qk, bool msk) {
    const float CLIPV = 1.0f - 1e-7f;
    qk = fminf(fmaxf(qk, -CLIPV), CLIPV);
    float gd = msk ? 10000.0f : acosf(qk);
    float t = 1.0f + gd;
    float t2 = t * t;
    return __fdividef(1.0f, t2 * t2 * t);
}

// ---------------------------------------------------------------------------
// Pass 0: pre-split Q,K -> global bf16 hi/lo planes
// ---------------------------------------------------------------------------
__global__ __launch_bounds__(256, 1)
void spop_pass0(const float* __restrict__ Q, const float* __restrict__ K)
{
    size_t t = (size_t)blockIdx.x * 256 + threadIdx.x;   // 0..262143, 8 floats each
    {
        float4 a = ((const float4*)Q)[t*2], b = ((const float4*)Q)[t*2+1];
        float f[8] = {a.x,a.y,a.z,a.w,b.x,b.y,b.z,b.w};
        uint4 H, L; split8(f, H, L);
        g_qh4[t] = H; g_ql4[t] = L;
    }
    {
        float4 a = ((const float4*)K)[t*2], b = ((const float4*)K)[t*2+1];
        float f[8] = {a.x,a.y,a.z,a.w,b.x,b.y,b.z,b.w};
        uint4 H, L; split8(f, H, L);
        g_kh4[t] = H; g_kl4[t] = L;
    }
}

// smem pass1
#define P1_KH 0
#define P1_KL 16384
#define P1_Q  32768           // + buf*32768 (+16384 for lo plane)
#define P1_RED 98304
#define P1_SMEM (98304 + 1024)

// ---------------------------------------------------------------------------
// Pass 1: qk = K[m,:]·Q[n,:] via HMMA bf16x2-split (hh + lh + hl),
//   cp.async double-buffered Q planes; store scores as bf16 hi/lo planes.
// ---------------------------------------------------------------------------
__global__ __launch_bounds__(256, 1)
void spop_pass1_mma(const int* __restrict__ mask)
{
    extern __shared__ char sm[];
    const uint32_t sb = smem_u32(sm);

    const int bh = blockIdx.y;
    const int b  = bh / HHEADS;
    const int m0 = blockIdx.x * 128;
    const int tid = threadIdx.x;
    const int lane = tid & 31;
    const int wid  = tid >> 5;
    const int wm = wid & 3;
    const int wn = wid >> 2;
    const int g   = lane >> 2;
    const int tig = lane & 3;

    // ---- cp.async K planes + Q(0) planes ----
    {
        #pragma unroll
        for (int i = 0; i < 4; i++) {
            int gr = tid + 256 * i;
            int row = gr >> 3, u = gr & 7;
            size_t sbyte = ((size_t)(bh * NSEQ + m0 + row) * DDIM) * 2 + (size_t)u * 16;
            uint32_t doff = SWZ128((uint32_t)(row * 128 + u * 16));
            cp16(sb + P1_KH + doff, (const char*)g_kh4 + sbyte);
            cp16(sb + P1_KL + doff, (const char*)g_kl4 + sbyte);
        }
        #pragma unroll
        for (int i = 0; i < 4; i++) {
            int gr = tid + 256 * i;
            int row = gr >> 3, u = gr & 7;
            size_t sbyte = ((size_t)(bh * NSEQ + row) * DDIM) * 2 + (size_t)u * 16;
            uint32_t doff = SWZ128((uint32_t)(row * 128 + u * 16));
            cp16(sb + P1_Q + doff,         (const char*)g_qh4 + sbyte);
            cp16(sb + P1_Q + 16384 + doff, (const char*)g_ql4 + sbyte);
        }
        CP_COMMIT();
    }

    bool mskf[4];
    #pragma unroll
    for (int q = 0; q < 4; q++) {
        int mloc = wm * 32 + (q >> 1) * 16 + (q & 1) * 8 + g;
        mskf[q] = (mask[b * NSEQ + m0 + mloc] == 0);
    }
    float rowacc[4] = {0.f, 0.f, 0.f, 0.f};

    const uint32_t a_row = (uint32_t)(wm * 32 + (lane & 15));
    const uint32_t a_k16 = (uint32_t)((lane >> 4) * 16);
    const uint32_t b_row = (uint32_t)(wn * 64 + ((lane >> 3) & 1) * 8 + (lane & 7));
    const uint32_t b_k16 = (uint32_t)((lane >> 4) * 16);

    for (int it = 0; it < NSEQ / 128; it++) {
        CP_WAIT0();          // Q(it) (and K on it=0) resident
        __syncthreads();     // + all warps done with MMA(it-1)

        // prefetch Q(it+1) into the other buffer (overlaps MMA+epilogue)
        if (it < 15) {
            uint32_t qb = sb + P1_Q + (uint32_t)(((it + 1) & 1) * 32768);
            #pragma unroll
            for (int i = 0; i < 4; i++) {
                int gr = tid + 256 * i;
                int row = gr >> 3, u = gr & 7;
                size_t sbyte = ((size_t)(bh * NSEQ + (it + 1) * 128 + row) * DDIM) * 2
                               + (size_t)u * 16;
                uint32_t doff = SWZ128((uint32_t)(row * 128 + u * 16));
                cp16(qb + doff,         (const char*)g_qh4 + sbyte);
                cp16(qb + 16384 + doff, (const char*)g_ql4 + sbyte);
            }
            CP_COMMIT();
        }

        const uint32_t qHb = sb + P1_Q + (uint32_t)((it & 1) * 32768);
        const uint32_t qLb = qHb + 16384;
        const uint32_t kHb = sb + P1_KH;
        const uint32_t kLb = sb + P1_KL;

        float acc[2][8][4];
        #pragma unroll
        for (int tm = 0; tm < 2; tm++)
            #pragma unroll
            for (int tn = 0; tn < 8; tn++)
                #pragma unroll
                for (int c = 0; c < 4; c++) acc[tm][tn][c] = 0.f;

        #pragma unroll
        for (int kc = 0; kc < 4; kc++) {
            uint32_t Ah[2][4], Al[2][4], Bq[4][4];
            const uint32_t kb = (uint32_t)(kc * 32) + a_k16;
            #pragma unroll
            for (int tm = 0; tm < 2; tm++)
                ldsm_x4(Ah[tm], kHb + SWZ128((a_row + tm*16) * 128 + kb));
            #pragma unroll
            for (int p = 0; p < 4; p++)
                ldsm_x4(Bq[p], qHb + SWZ128((b_row + p*16) * 128 + (uint32_t)(kc*32) + b_k16));
            #pragma unroll
            for (int tm = 0; tm < 2; tm++)
                #pragma unroll
                for (int tn = 0; tn < 8; tn++)
                    mma_bf16(acc[tm][tn], Ah[tm],
                             Bq[tn>>1][(tn&1)], Bq[tn>>1][2 + (tn&1)]);
            #pragma unroll
            for (int tm = 0; tm < 2; tm++)
                ldsm_x4(Al[tm], kLb + SWZ128((a_row + tm*16) * 128 + kb));
            #pragma unroll
            for (int tm = 0; tm < 2; tm++)
                #pragma unroll
                for (int tn = 0; tn < 8; tn++)
                    mma_bf16(acc[tm][tn], Al[tm],
                             Bq[tn>>1][(tn&1)], Bq[tn>>1][2 + (tn&1)]);
            #pragma unroll
            for (int p = 0; p < 4; p++)
                ldsm_x4(Bq[p], qLb + SWZ128((b_row + p*16) * 128 + (uint32_t)(kc*32) + b_k16));
            #pragma unroll
            for (int tm = 0; tm < 2; tm++)
                #pragma unroll
                for (int tn = 0; tn < 8; tn++)
                    mma_bf16(acc[tm][tn], Ah[tm],
                             Bq[tn>>1][(tn&1)], Bq[tn>>1][2 + (tn&1)]);
        }

        // ---- epilogue: transform, split to bf16 hi/lo planes, column sums ----
        const int n0 = it * 128;
        #pragma unroll
        for (int tm = 0; tm < 2; tm++) {
            #pragma unroll
            for (int h = 0; h < 2; h++) {
                const int q = tm * 2 + h;
                const int mloc = wm * 32 + tm * 16 + h * 8 + g;
                const bool mk = mskf[q];
                size_t rowbase = ((size_t)bh * NSEQ + m0 + mloc) * NSEQ
                                 + n0 + wn * 64 + 2 * tig;
                uint32_t* dH = (uint32_t*)g_sH4 + (rowbase >> 1);
                uint32_t* dL = (uint32_t*)g_sL4 + (rowbase >> 1);
                float racc = 0.f;
                #pragma unroll
                for (int tn = 0; tn < 8; tn++) {
                    float s0 = score_fn(acc[tm][tn][2*h],     mk);
                    float s1 = score_fn(acc[tm][tn][2*h + 1], mk);
                    racc += s0 + s1;
                    __nv_bfloat16 h0 = __float2bfloat16(s0);
                    __nv_bfloat16 h1 = __float2bfloat16(s1);
                    float l0 = s0 - __bfloat162float(h0);
                    float l1 = s1 - __bfloat162float(h1);
                    dH[tn * 4] = bfu(h0) | (bfu(h1) << 16);
                    dL[tn * 4] = bfu(__float2bfloat16(l0)) |
                                 (bfu(__float2bfloat16(l1)) << 16);
                }
                rowacc[q] += racc;
            }
        }
    }

    #pragma unroll
    for (int q = 0; q < 4; q++) {
        rowacc[q] += __shfl_xor_sync(0xffffffffu, rowacc[q], 1);
        rowacc[q] += __shfl_xor_sync(0xffffffffu, rowacc[q], 2);
    }
    float* red = (float*)(sm + P1_RED);
    __syncthreads();
    if (tig == 0) {
        #pragma unroll
        for (int q = 0; q < 4; q++) {
            int mloc = wm * 32 + (q >> 1) * 16 + (q & 1) * 8 + g;
            red[wn * 128 + mloc] = rowacc[q];
        }
    }
    __syncthreads();
    if (tid < 128)
        g_ncinv[bh * NSEQ + m0 + tid] = rsqrtf(red[tid] + red[128 + tid]);
}

// smem pass2
#define P2_W   0              // + buf*65536 (+32768 for lo plane)
#define P2_VH  131072
#define P2_VL  149504
#define P2_SMEM 167936
#define VSTRIDE 144

// ---------------------------------------------------------------------------
// Pass 2: out[n,:] = (Σ_m s·(nci·V)) / (Σ_m s·nci)
//   W planes via double-buffered cp.async, nci folded into V (+ones col).
// ---------------------------------------------------------------------------
__global__ __launch_bounds__(256, 1)
void spop_pass2_mma(const float* __restrict__ V,
                    float*       __restrict__ out)
{
    extern __shared__ char sm[];
    const uint32_t sb = smem_u32(sm);

    const int bh = blockIdx.y;
    const int n0 = blockIdx.x * 128;
    const int tid = threadIdx.x;
    const int lane = tid & 31;
    const int wid  = tid >> 5;
    const int wrow = wid * 16;
    const int g = lane >> 2, tig = lane & 3;

    float acc[9][4];
    #pragma unroll
    for (int dt = 0; dt < 9; dt++)
        #pragma unroll
        for (int c = 0; c < 4; c++) acc[dt][c] = 0.f;

    const uint32_t a_min  = (uint32_t)((lane & 7) + ((lane >> 4) & 1) * 8);
    const uint32_t a_noff = (uint32_t)(((lane >> 3) & 1) * 8);
    const uint32_t b_kin  = (uint32_t)((lane & 7) + ((lane >> 3) & 1) * 8);
    const uint32_t b_doff = (uint32_t)((lane >> 4) * 8);
    const uint32_t b_kin2 = (uint32_t)(lane & 15);

    // prologue: cp.async W chunk 0
    {
        const size_t cbase = ((size_t)bh * NSEQ) * NSEQ + n0;
        #pragma unroll
        for (int i = 0; i < 8; i++) {
            int gr = tid + 256 * i;
            int row = gr >> 4, u = gr & 15;
            size_t sbyte = (cbase + (size_t)row * NSEQ) * 2 + (size_t)u * 16;
            uint32_t doff = SWZ256((uint32_t)(row * 256 + u * 16));
            cp16(sb + doff,         (const char*)g_sH4 + sbyte);
            cp16(sb + 32768 + doff, (const char*)g_sL4 + sbyte);
        }
        CP_COMMIT();
    }

    const int vr = tid >> 1, vhalf = tid & 1;

    for (int it = 0; it < NSEQ / 128; it++) {
        const int m0 = it * 128;

        // V row fp32 -> regs (overlaps wait)
        float f[32];
        const float nci = g_ncinv[bh * NSEQ + m0 + vr];
        {
            const float4* Vg = (const float4*)(V + ((size_t)bh * NSEQ + m0 + vr) * DDIM
                                               + vhalf * 32);
            #pragma unroll
            for (int i = 0; i < 8; i++) {
                float4 v = Vg[i];
                f[4*i] = v.x * nci; f[4*i+1] = v.y * nci;
                f[4*i+2] = v.z * nci; f[4*i+3] = v.w * nci;
            }
        }

        CP_WAIT0();          // W(it) resident
        __syncthreads();     // + all warps done MMA(it-1)

        // prefetch W(it+1) (other buffer; overlaps STS + MMA)
        if (it < 15) {
            uint32_t wb = sb + (uint32_t)(((it + 1) & 1) * 65536);
            const size_t cbase = ((size_t)bh * NSEQ + (it + 1) * 128) * NSEQ + n0;
            #pragma unroll
            for (int i = 0; i < 8; i++) {
                int gr = tid + 256 * i;
                int row = gr >> 4, u = gr & 15;
                size_t sbyte = (cbase + (size_t)row * NSEQ) * 2 + (size_t)u * 16;
                uint32_t doff = SWZ256((uint32_t)(row * 256 + u * 16));
                cp16(wb + doff,         (const char*)g_sH4 + sbyte);
                cp16(wb + 32768 + doff, (const char*)g_sL4 + sbyte);
            }
            CP_COMMIT();
        }

        // V' split -> smem (+ ones*nci column)
        {
            #pragma unroll
            for (int u = 0; u < 4; u++) {
                uint4 H, L;
                split8(f + 8*u, H, L);
                uint32_t off = (uint32_t)(vr * VSTRIDE + vhalf * 64 + u * 16);
                *(uint4*)(sm + P2_VH + off) = H;
                *(uint4*)(sm + P2_VL + off) = L;
            }
            if (vhalf == 1) {
                __nv_bfloat16 nh = __float2bfloat16(nci);
                float nlr = nci - __bfloat162float(nh);
                uint32_t off = (uint32_t)(vr * VSTRIDE + 128);
                *(uint4*)(sm + P2_VH + off) = make_uint4(bfu(nh), 0u, 0u, 0u);
                *(uint4*)(sm + P2_VL + off) =
                    make_uint4(bfu(__float2bfloat16(nlr)), 0u, 0u, 0u);
            }
        }
        __syncthreads();

        const uint32_t wHb = sb + (uint32_t)((it & 1) * 65536);
        const uint32_t wLb = wHb + 32768;

        #pragma unroll
        for (int kc = 0; kc < 8; kc++) {
            uint32_t Awh[4], Awl[4], Bv[4][4], Bv8[2];
            const uint32_t mbyte = ((uint32_t)(kc * 16) + a_min) * 256;
            const uint32_t nbyte = ((uint32_t)wrow + a_noff) * 2;
            ldsm_x4_t(Awh, wHb + SWZ256(mbyte + nbyte));
            #pragma unroll
            for (int p = 0; p < 4; p++)
                ldsm_x4_t(Bv[p], sb + P2_VH + ((uint32_t)(kc*16) + b_kin) * VSTRIDE
                                + (uint32_t)(p * 32) + b_doff * 2);
            ldsm_x2_t(Bv8, sb + P2_VH + ((uint32_t)(kc*16) + b_kin2) * VSTRIDE + 128);
            // Wh * V'h
            #pragma unroll
            for (int dt = 0; dt < 8; dt++)
                mma_bf16(acc[dt], Awh, Bv[dt>>1][(dt&1)*2], Bv[dt>>1][(dt&1)*2+1]);
            mma_bf16(acc[8], Awh, Bv8[0], Bv8[1]);
            // Wl * V'h
            ldsm_x4_t(Awl, wLb + SWZ256(mbyte + nbyte));
            #pragma unroll
            for (int dt = 0; dt < 8; dt++)
                mma_bf16(acc[dt], Awl, Bv[dt>>1][(dt&1)*2], Bv[dt>>1][(dt&1)*2+1]);
            mma_bf16(acc[8], Awl, Bv8[0], Bv8[1]);
            // Wh * V'l
            #pragma unroll
            for (int p = 0; p < 4; p++)
                ldsm_x4_t(Bv[p], sb + P2_VL + ((uint32_t)(kc*16) + b_kin) * VSTRIDE
                                + (uint32_t)(p * 32) + b_doff * 2);
            ldsm_x2_t(Bv8, sb + P2_VL + ((uint32_t)(kc*16) + b_kin2) * VSTRIDE + 128);
            #pragma unroll
            for (int dt = 0; dt < 8; dt++)
                mma_bf16(acc[dt], Awh, Bv[dt>>1][(dt&1)*2], Bv[dt>>1][(dt&1)*2+1]);
            mma_bf16(acc[8], Awh, Bv8[0], Bv8[1]);
        }
    }

    // epilogue: divide by row sums (ones column), store
    const int srcl = lane & ~3;
    float sum0 = __shfl_sync(0xffffffffu, acc[8][0], srcl);
    float sum1 = __shfl_sync(0xffffffffu, acc[8][2], srcl);
    float inv0 = __fdividef(1.0f, sum0);
    float inv1 = __fdividef(1.0f, sum1);

    const int ng0 = n0 + wrow + g;
    float* O0 = out + ((size_t)bh * NSEQ + ng0) * DDIM + 2 * tig;
    float* O1 = out + ((size_t)bh * NSEQ + ng0 + 8) * DDIM + 2 * tig;
    #pragma unroll
    for (int dt = 0; dt < 8; dt++) {
        *(float2*)(O0 + dt * 8) = make_float2(acc[dt][0] * inv0, acc[dt][1] * inv0);
        *(float2*)(O1 + dt * 8) = make_float2(acc[dt][2] * inv1, acc[dt][3] * inv1);
    }
}

// ---------------------------------------------------------------------------
extern "C" void kernel_launch(void* const* d_in, const int* in_sizes, int n_in,
                              void* d_out, int out_size)
{
    const float* Q    = (const float*)d_in[0];
    const float* K    = (const float*)d_in[1];
    const float* V    = (const float*)d_in[2];
    const int*   mask = (const int*)d_in[3];
    float*       out  = (float*)d_out;

    cudaFuncSetAttribute(spop_pass1_mma, cudaFuncAttributeMaxDynamicSharedMemorySize, P1_SMEM);
    cudaFuncSetAttribute(spop_pass2_mma, cudaFuncAttributeMaxDynamicSharedMemorySize, P2_SMEM);

    dim3 grid(NSEQ / 128, BHN);
    spop_pass0<<<(int)(QK_ELEMS / 8 / 256), 256>>>(Q, K);
    spop_pass1_mma<<<grid, 256, P1_SMEM>>>(mask);
    spop_pass2_mma<<<grid, 256, P2_SMEM>>>(V, out);
}

// round 6
// speedup vs baseline: 2.0337x; 1.1769x over previous
#include <cuda_runtime.h>
#include <cuda_bf16.h>
#include <cuda_fp16.h>
#include <math.h>
#include <cstdint>

#define NSEQ 2048
#define DDIM 64
#define HHEADS 8
#define BHN 16

#define QK_ELEMS ((size_t)BHN * NSEQ * DDIM)
#define S_ELEMS  ((size_t)BHN * NSEQ * NSEQ)

// pre-split bf16 hi/lo planes for Q,K
__device__ uint4 g_qh4[QK_ELEMS / 8], g_ql4[QK_ELEMS / 8];
__device__ uint4 g_kh4[QK_ELEMS / 8], g_kl4[QK_ELEMS / 8];
// scores: single fp16 plane [bh][m][n]
__device__ uint4 g_sF4[S_ELEMS / 8];
__device__ float g_ncinv[BHN * NSEQ];

// ---------------------------------------------------------------------------
__device__ __forceinline__ uint32_t smem_u32(const void* p) {
    uint32_t a;
    asm("{ .reg .u64 t; cvta.to.shared.u64 t, %1; cvt.u32.u64 %0, t; }"
        : "=r"(a) : "l"(p));
    return a;
}
__device__ __forceinline__ void ldsm_x4(uint32_t r[4], uint32_t a) {
    asm volatile("ldmatrix.sync.aligned.m8n8.x4.shared.b16 {%0,%1,%2,%3}, [%4];"
        : "=r"(r[0]), "=r"(r[1]), "=r"(r[2]), "=r"(r[3]) : "r"(a));
}
__device__ __forceinline__ void ldsm_x4_t(uint32_t r[4], uint32_t a) {
    asm volatile("ldmatrix.sync.aligned.m8n8.x4.trans.shared.b16 {%0,%1,%2,%3}, [%4];"
        : "=r"(r[0]), "=r"(r[1]), "=r"(r[2]), "=r"(r[3]) : "r"(a));
}
__device__ __forceinline__ void ldsm_x2_t(uint32_t r[2], uint32_t a) {
    asm volatile("ldmatrix.sync.aligned.m8n8.x2.trans.shared.b16 {%0,%1}, [%2];"
        : "=r"(r[0]), "=r"(r[1]) : "r"(a));
}
__device__ __forceinline__ void mma_bf16(float c[4], const uint32_t a[4],
                                         uint32_t b0, uint32_t b1) {
    asm volatile("mma.sync.aligned.m16n8k16.row.col.f32.bf16.bf16.f32 "
        "{%0,%1,%2,%3}, {%4,%5,%6,%7}, {%8,%9}, {%0,%1,%2,%3};"
        : "+f"(c[0]), "+f"(c[1]), "+f"(c[2]), "+f"(c[3])
        : "r"(a[0]), "r"(a[1]), "r"(a[2]), "r"(a[3]), "r"(b0), "r"(b1));
}
__device__ __forceinline__ void mma_f16(float c[4], const uint32_t a[4],
                                        uint32_t b0, uint32_t b1) {
    asm volatile("mma.sync.aligned.m16n8k16.row.col.f32.f16.f16.f32 "
        "{%0,%1,%2,%3}, {%4,%5,%6,%7}, {%8,%9}, {%0,%1,%2,%3};"
        : "+f"(c[0]), "+f"(c[1]), "+f"(c[2]), "+f"(c[3])
        : "r"(a[0]), "r"(a[1]), "r"(a[2]), "r"(a[3]), "r"(b0), "r"(b1));
}
__device__ __forceinline__ void cp16(uint32_t dst, const void* src) {
    asm volatile("cp.async.cg.shared.global [%0], [%1], 16;"
        :: "r"(dst), "l"(src) : "memory");
}
#define CP_COMMIT() asm volatile("cp.async.commit_group;" ::: "memory")
#define CP_WAIT0()  asm volatile("cp.async.wait_group 0;" ::: "memory")

#define SWZ128(o) ((o) ^ (((o) >> 3) & 0x70))
#define SWZ256(o) ((o) ^ (((o) >> 4) & 0x70))

__device__ __forceinline__ uint32_t bfu(__nv_bfloat16 h) {
    return (uint32_t)__bfloat16_as_ushort(h);
}
__device__ __forceinline__ void split8(const float* f, uint4& H, uint4& L) {
    uint32_t h[4], l[4];
    #pragma unroll
    for (int p = 0; p < 4; p++) {
        float x0 = f[2*p], x1 = f[2*p+1];
        __nv_bfloat16 h0 = __float2bfloat16(x0);
        __nv_bfloat16 h1 = __float2bfloat16(x1);
        h[p] = bfu(h0) | (bfu(h1) << 16);
        float r0 = x0 - __bfloat162float(h0);
        float r1 = x1 - __bfloat162float(h1);
        l[p] = bfu(__float2bfloat16(r0)) | (bfu(__float2bfloat16(r1)) << 16);
    }
    H = make_uint4(h[0], h[1], h[2], h[3]);
    L = make_uint4(l[0], l[1], l[2], l[3]);
}
__device__ __forceinline__ uint32_t h2u(__half2 h) {
    return *reinterpret_cast<uint32_t*>(&h);
}

__device__ __forceinline__ float score_fn(float qk, bool msk) {
    const float CLIPV = 1.0f - 1e-7f;
    qk = fminf(fmaxf(qk, -CLIPV), CLIPV);
    float gd = msk ? 10000.0f : acosf(qk);
    float t = 1.0f + gd;
    float t2 = t * t;
    return __fdividef(1.0f, t2 * t2 * t);
}

// ---------------------------------------------------------------------------
// Pass 0: pre-split Q,K -> global bf16 hi/lo planes
// ---------------------------------------------------------------------------
__global__ __launch_bounds__(256, 1)
void spop_pass0(const float* __restrict__ Q, const float* __restrict__ K)
{
    size_t t = (size_t)blockIdx.x * 256 + threadIdx.x;
    {
        float4 a = ((const float4*)Q)[t*2], b = ((const float4*)Q)[t*2+1];
        float f[8] = {a.x,a.y,a.z,a.w,b.x,b.y,b.z,b.w};
        uint4 H, L; split8(f, H, L);
        g_qh4[t] = H; g_ql4[t] = L;
    }
    {
        float4 a = ((const float4*)K)[t*2], b = ((const float4*)K)[t*2+1];
        float f[8] = {a.x,a.y,a.z,a.w,b.x,b.y,b.z,b.w};
        uint4 H, L; split8(f, H, L);
        g_kh4[t] = H; g_kl4[t] = L;
    }
}

// smem pass1
#define P1_KH 0
#define P1_KL 16384
#define P1_Q  32768
#define P1_RED 98304
#define P1_SMEM (98304 + 1024)

// ---------------------------------------------------------------------------
// Pass 1: qk = K[m,:]·Q[n,:] via HMMA bf16x2 (hh + lh + hl); scores -> fp16.
//   ncinv[m] zeroed for masked m (true contribution ~1e-12, prevents fp16
//   overflow of nci*V in pass 2).
// ---------------------------------------------------------------------------
__global__ __launch_bounds__(256, 1)
void spop_pass1_mma(const int* __restrict__ mask)
{
    extern __shared__ char sm[];
    const uint32_t sb = smem_u32(sm);

    const int bh = blockIdx.y;
    const int b  = bh / HHEADS;
    const int m0 = blockIdx.x * 128;
    const int tid = threadIdx.x;
    const int lane = tid & 31;
    const int wid  = tid >> 5;
    const int wm = wid & 3;
    const int wn = wid >> 2;
    const int g   = lane >> 2;
    const int tig = lane & 3;

    {
        #pragma unroll
        for (int i = 0; i < 4; i++) {
            int gr = tid + 256 * i;
            int row = gr >> 3, u = gr & 7;
            size_t sbyte = ((size_t)(bh * NSEQ + m0 + row) * DDIM) * 2 + (size_t)u * 16;
            uint32_t doff = SWZ128((uint32_t)(row * 128 + u * 16));
            cp16(sb + P1_KH + doff, (const char*)g_kh4 + sbyte);
            cp16(sb + P1_KL + doff, (const char*)g_kl4 + sbyte);
        }
        #pragma unroll
        for (int i = 0; i < 4; i++) {
            int gr = tid + 256 * i;
            int row = gr >> 3, u = gr & 7;
            size_t sbyte = ((size_t)(bh * NSEQ + row) * DDIM) * 2 + (size_t)u * 16;
            uint32_t doff = SWZ128((uint32_t)(row * 128 + u * 16));
            cp16(sb + P1_Q + doff,         (const char*)g_qh4 + sbyte);
            cp16(sb + P1_Q + 16384 + doff, (const char*)g_ql4 + sbyte);
        }
        CP_COMMIT();
    }

    bool mskf[4];
    #pragma unroll
    for (int q = 0; q < 4; q++) {
        int mloc = wm * 32 + (q >> 1) * 16 + (q & 1) * 8 + g;
        mskf[q] = (mask[b * NSEQ + m0 + mloc] == 0);
    }
    float rowacc[4] = {0.f, 0.f, 0.f, 0.f};

    const uint32_t a_row = (uint32_t)(wm * 32 + (lane & 15));
    const uint32_t a_k16 = (uint32_t)((lane >> 4) * 16);
    const uint32_t b_row = (uint32_t)(wn * 64 + ((lane >> 3) & 1) * 8 + (lane & 7));
    const uint32_t b_k16 = (uint32_t)((lane >> 4) * 16);

    for (int it = 0; it < NSEQ / 128; it++) {
        CP_WAIT0();
        __syncthreads();

        if (it < 15) {
            uint32_t qb = sb + P1_Q + (uint32_t)(((it + 1) & 1) * 32768);
            #pragma unroll
            for (int i = 0; i < 4; i++) {
                int gr = tid + 256 * i;
                int row = gr >> 3, u = gr & 7;
                size_t sbyte = ((size_t)(bh * NSEQ + (it + 1) * 128 + row) * DDIM) * 2
                               + (size_t)u * 16;
                uint32_t doff = SWZ128((uint32_t)(row * 128 + u * 16));
                cp16(qb + doff,         (const char*)g_qh4 + sbyte);
                cp16(qb + 16384 + doff, (const char*)g_ql4 + sbyte);
            }
            CP_COMMIT();
        }

        const uint32_t qHb = sb + P1_Q + (uint32_t)((it & 1) * 32768);
        const uint32_t qLb = qHb + 16384;
        const uint32_t kHb = sb + P1_KH;
        const uint32_t kLb = sb + P1_KL;

        float acc[2][8][4];
        #pragma unroll
        for (int tm = 0; tm < 2; tm++)
            #pragma unroll
            for (int tn = 0; tn < 8; tn++)
                #pragma unroll
                for (int c = 0; c < 4; c++) acc[tm][tn][c] = 0.f;

        #pragma unroll
        for (int kc = 0; kc < 4; kc++) {
            uint32_t Ah[2][4], Al[2][4], Bq[4][4];
            const uint32_t kb = (uint32_t)(kc * 32) + a_k16;
            #pragma unroll
            for (int tm = 0; tm < 2; tm++)
                ldsm_x4(Ah[tm], kHb + SWZ128((a_row + tm*16) * 128 + kb));
            #pragma unroll
            for (int p = 0; p < 4; p++)
                ldsm_x4(Bq[p], qHb + SWZ128((b_row + p*16) * 128 + (uint32_t)(kc*32) + b_k16));
            #pragma unroll
            for (int tm = 0; tm < 2; tm++)
                #pragma unroll
                for (int tn = 0; tn < 8; tn++)
                    mma_bf16(acc[tm][tn], Ah[tm],
                             Bq[tn>>1][(tn&1)], Bq[tn>>1][2 + (tn&1)]);
            #pragma unroll
            for (int tm = 0; tm < 2; tm++)
                ldsm_x4(Al[tm], kLb + SWZ128((a_row + tm*16) * 128 + kb));
            #pragma unroll
            for (int tm = 0; tm < 2; tm++)
                #pragma unroll
                for (int tn = 0; tn < 8; tn++)
                    mma_bf16(acc[tm][tn], Al[tm],
                             Bq[tn>>1][(tn&1)], Bq[tn>>1][2 + (tn&1)]);
            #pragma unroll
            for (int p = 0; p < 4; p++)
                ldsm_x4(Bq[p], qLb + SWZ128((b_row + p*16) * 128 + (uint32_t)(kc*32) + b_k16));
            #pragma unroll
            for (int tm = 0; tm < 2; tm++)
                #pragma unroll
                for (int tn = 0; tn < 8; tn++)
                    mma_bf16(acc[tm][tn], Ah[tm],
                             Bq[tn>>1][(tn&1)], Bq[tn>>1][2 + (tn&1)]);
        }

        // ---- epilogue: transform -> fp16 plane + column sums ----
        const int n0 = it * 128;
        #pragma unroll
        for (int tm = 0; tm < 2; tm++) {
            #pragma unroll
            for (int h = 0; h < 2; h++) {
                const int q = tm * 2 + h;
                const int mloc = wm * 32 + tm * 16 + h * 8 + g;
                const bool mk = mskf[q];
                size_t rowbase = ((size_t)bh * NSEQ + m0 + mloc) * NSEQ
                                 + n0 + wn * 64 + 2 * tig;
                uint32_t* dF = (uint32_t*)g_sF4 + (rowbase >> 1);
                float racc = 0.f;
                #pragma unroll
                for (int tn = 0; tn < 8; tn++) {
                    float s0 = score_fn(acc[tm][tn][2*h],     mk);
                    float s1 = score_fn(acc[tm][tn][2*h + 1], mk);
                    racc += s0 + s1;
                    dF[tn * 4] = h2u(__floats2half2_rn(s0, s1));
                }
                rowacc[q] += racc;
            }
        }
    }

    #pragma unroll
    for (int q = 0; q < 4; q++) {
        rowacc[q] += __shfl_xor_sync(0xffffffffu, rowacc[q], 1);
        rowacc[q] += __shfl_xor_sync(0xffffffffu, rowacc[q], 2);
    }
    float* red = (float*)(sm + P1_RED);
    __syncthreads();
    if (tig == 0) {
        #pragma unroll
        for (int q = 0; q < 4; q++) {
            int mloc = wm * 32 + (q >> 1) * 16 + (q & 1) * 8 + g;
            red[wn * 128 + mloc] = rowacc[q];
        }
    }
    __syncthreads();
    if (tid < 128) {
        // masked columns: true weight ~1e-12 of row sums -> zero them to keep
        // nci*V inside fp16 range in pass 2.
        bool mk = (mask[b * NSEQ + m0 + tid] == 0);
        float nci = mk ? 0.0f : rsqrtf(red[tid] + red[128 + tid]);
        g_ncinv[bh * NSEQ + m0 + tid] = nci;
    }
}

// smem pass2: W double buffer (32KB each) + V fp16 plane
#define P2_V   65536
#define P2_SMEM (65536 + 18432)
#define VSTRIDE 144   // 72 halves per row

// ---------------------------------------------------------------------------
// Pass 2: out[n,:] = (Σ_m s·(nci·V)) / (Σ_m s·nci); all-fp16 operands.
// ---------------------------------------------------------------------------
__global__ __launch_bounds__(256, 1)
void spop_pass2_mma(const float* __restrict__ V,
                    float*       __restrict__ out)
{
    extern __shared__ char sm[];
    const uint32_t sb = smem_u32(sm);

    const int bh = blockIdx.y;
    const int n0 = blockIdx.x * 128;
    const int tid = threadIdx.x;
    const int lane = tid & 31;
    const int wid  = tid >> 5;
    const int wrow = wid * 16;
    const int g = lane >> 2, tig = lane & 3;

    float acc[9][4];
    #pragma unroll
    for (int dt = 0; dt < 9; dt++)
        #pragma unroll
        for (int c = 0; c < 4; c++) acc[dt][c] = 0.f;

    const uint32_t a_min  = (uint32_t)((lane & 7) + ((lane >> 4) & 1) * 8);
    const uint32_t a_noff = (uint32_t)(((lane >> 3) & 1) * 8);
    const uint32_t b_kin  = (uint32_t)((lane & 7) + ((lane >> 3) & 1) * 8);
    const uint32_t b_doff = (uint32_t)((lane >> 4) * 8);
    const uint32_t b_kin2 = (uint32_t)(lane & 15);

    // prologue: cp.async W chunk 0 (single fp16 plane, 32KB)
    {
        const size_t cbase = ((size_t)bh * NSEQ) * NSEQ + n0;
        #pragma unroll
        for (int i = 0; i < 8; i++) {
            int gr = tid + 256 * i;
            int row = gr >> 4, u = gr & 15;
            size_t sbyte = (cbase + (size_t)row * NSEQ) * 2 + (size_t)u * 16;
            uint32_t doff = SWZ256((uint32_t)(row * 256 + u * 16));
            cp16(sb + doff, (const char*)g_sF4 + sbyte);
        }
        CP_COMMIT();
    }

    const int vr = tid >> 1, vhalf = tid & 1;

    for (int it = 0; it < NSEQ / 128; it++) {
        const int m0 = it * 128;

        // V row fp32 -> regs, scaled by nci (overlaps wait)
        float f[32];
        const float nci = g_ncinv[bh * NSEQ + m0 + vr];
        {
            const float4* Vg = (const float4*)(V + ((size_t)bh * NSEQ + m0 + vr) * DDIM
                                               + vhalf * 32);
            #pragma unroll
            for (int i = 0; i < 8; i++) {
                float4 v = Vg[i];
                f[4*i] = v.x * nci; f[4*i+1] = v.y * nci;
                f[4*i+2] = v.z * nci; f[4*i+3] = v.w * nci;
            }
        }

        CP_WAIT0();
        __syncthreads();

        // prefetch W(it+1)
        if (it < 15) {
            uint32_t wb = sb + (uint32_t)(((it + 1) & 1) * 32768);
            const size_t cbase = ((size_t)bh * NSEQ + (it + 1) * 128) * NSEQ + n0;
            #pragma unroll
            for (int i = 0; i < 8; i++) {
                int gr = tid + 256 * i;
                int row = gr >> 4, u = gr & 15;
                size_t sbyte = (cbase + (size_t)row * NSEQ) * 2 + (size_t)u * 16;
                uint32_t doff = SWZ256((uint32_t)(row * 256 + u * 16));
                cp16(wb + doff, (const char*)g_sF4 + sbyte);
            }
            CP_COMMIT();
        }

        // V' -> fp16 smem (+ nci in ones column)
        {
            #pragma unroll
            for (int u = 0; u < 4; u++) {
                uint32_t p0 = h2u(__floats2half2_rn(f[8*u+0], f[8*u+1]));
                uint32_t p1 = h2u(__floats2half2_rn(f[8*u+2], f[8*u+3]));
                uint32_t p2 = h2u(__floats2half2_rn(f[8*u+4], f[8*u+5]));
                uint32_t p3 = h2u(__floats2half2_rn(f[8*u+6], f[8*u+7]));
                uint32_t off = (uint32_t)(vr * VSTRIDE + vhalf * 64 + u * 16);
                *(uint4*)(sm + P2_V + off) = make_uint4(p0, p1, p2, p3);
            }
            if (vhalf == 1) {
                uint32_t nb = h2u(__floats2half2_rn(nci, 0.0f));
                uint32_t off = (uint32_t)(vr * VSTRIDE + 128);
                *(uint4*)(sm + P2_V + off) = make_uint4(nb, 0u, 0u, 0u);
            }
        }
        __syncthreads();

        const uint32_t wB = sb + (uint32_t)((it & 1) * 32768);

        #pragma unroll
        for (int kc = 0; kc < 8; kc++) {
            uint32_t Aw[4], Bv[4][4], Bv8[2];
            const uint32_t mbyte = ((uint32_t)(kc * 16) + a_min) * 256;
            const uint32_t nbyte = ((uint32_t)wrow + a_noff) * 2;
            ldsm_x4_t(Aw, wB + SWZ256(mbyte + nbyte));
            #pragma unroll
            for (int p = 0; p < 4; p++)
                ldsm_x4_t(Bv[p], sb + P2_V + ((uint32_t)(kc*16) + b_kin) * VSTRIDE
                                + (uint32_t)(p * 32) + b_doff * 2);
            ldsm_x2_t(Bv8, sb + P2_V + ((uint32_t)(kc*16) + b_kin2) * VSTRIDE + 128);
            #pragma unroll
            for (int dt = 0; dt < 8; dt++)
                mma_f16(acc[dt], Aw, Bv[dt>>1][(dt&1)*2], Bv[dt>>1][(dt&1)*2+1]);
            mma_f16(acc[8], Aw, Bv8[0], Bv8[1]);
        }
    }

    const int srcl = lane & ~3;
    float sum0 = __shfl_sync(0xffffffffu, acc[8][0], srcl);
    float sum1 = __shfl_sync(0xffffffffu, acc[8][2], srcl);
    float inv0 = __fdividef(1.0f, sum0);
    float inv1 = __fdividef(1.0f, sum1);

    const int ng0 = n0 + wrow + g;
    float* O0 = out + ((size_t)bh * NSEQ + ng0) * DDIM + 2 * tig;
    float* O1 = out + ((size_t)bh * NSEQ + ng0 + 8) * DDIM + 2 * tig;
    #pragma unroll
    for (int dt = 0; dt < 8; dt++) {
        *(float2*)(O0 + dt * 8) = make_float2(acc[dt][0] * inv0, acc[dt][1] * inv0);
        *(float2*)(O1 + dt * 8) = make_float2(acc[dt][2] * inv1, acc[dt][3] * inv1);
    }
}

// ---------------------------------------------------------------------------
extern "C" void kernel_launch(void* const* d_in, const int* in_sizes, int n_in,
                              void* d_out, int out_size)
{
    const float* Q    = (const float*)d_in[0];
    const float* K    = (const float*)d_in[1];
    const float* V    = (const float*)d_in[2];
    const int*   mask = (const int*)d_in[3];
    float*       out  = (float*)d_out;

    cudaFuncSetAttribute(spop_pass1_mma, cudaFuncAttributeMaxDynamicSharedMemorySize, P1_SMEM);
    cudaFuncSetAttribute(spop_pass2_mma, cudaFuncAttributeMaxDynamicSharedMemorySize, P2_SMEM);

    dim3 grid(NSEQ / 128, BHN);
    spop_pass0<<<(int)(QK_ELEMS / 8 / 256), 256>>>(Q, K);
    spop_pass1_mma<<<grid, 256, P1_SMEM>>>(mask);
    spop_pass2_mma<<<grid, 256, P2_SMEM>>>(V, out);
}

// round 7
// speedup vs baseline: 2.5055x; 1.2320x over previous
#include <cuda_runtime.h>
#include <cuda_bf16.h>
#include <cuda_fp16.h>
#include <math.h>
#include <cstdint>

#define NSEQ 2048
#define DDIM 64
#define HHEADS 8
#define BHN 16

#define QK_ELEMS ((size_t)BHN * NSEQ * DDIM)
#define S_ELEMS  ((size_t)BHN * NSEQ * NSEQ)

__device__ uint4 g_qh4[QK_ELEMS / 8], g_ql4[QK_ELEMS / 8];
__device__ uint4 g_kh4[QK_ELEMS / 8], g_kl4[QK_ELEMS / 8];
__device__ uint4 g_sF4[S_ELEMS / 8];          // fp16 scores [bh][m][n]
__device__ float g_ncinv[BHN * NSEQ];

// ---------------------------------------------------------------------------
__device__ __forceinline__ uint32_t smem_u32(const void* p) {
    uint32_t a;
    asm("{ .reg .u64 t; cvta.to.shared.u64 t, %1; cvt.u32.u64 %0, t; }"
        : "=r"(a) : "l"(p));
    return a;
}
__device__ __forceinline__ void ldsm_x4(uint32_t r[4], uint32_t a) {
    asm volatile("ldmatrix.sync.aligned.m8n8.x4.shared.b16 {%0,%1,%2,%3}, [%4];"
        : "=r"(r[0]), "=r"(r[1]), "=r"(r[2]), "=r"(r[3]) : "r"(a));
}
__device__ __forceinline__ void ldsm_x4_t(uint32_t r[4], uint32_t a) {
    asm volatile("ldmatrix.sync.aligned.m8n8.x4.trans.shared.b16 {%0,%1,%2,%3}, [%4];"
        : "=r"(r[0]), "=r"(r[1]), "=r"(r[2]), "=r"(r[3]) : "r"(a));
}
__device__ __forceinline__ void ldsm_x2_t(uint32_t r[2], uint32_t a) {
    asm volatile("ldmatrix.sync.aligned.m8n8.x2.trans.shared.b16 {%0,%1}, [%2];"
        : "=r"(r[0]), "=r"(r[1]) : "r"(a));
}
__device__ __forceinline__ void mma_bf16(float c[4], const uint32_t a[4],
                                         uint32_t b0, uint32_t b1) {
    asm volatile("mma.sync.aligned.m16n8k16.row.col.f32.bf16.bf16.f32 "
        "{%0,%1,%2,%3}, {%4,%5,%6,%7}, {%8,%9}, {%0,%1,%2,%3};"
        : "+f"(c[0]), "+f"(c[1]), "+f"(c[2]), "+f"(c[3])
        : "r"(a[0]), "r"(a[1]), "r"(a[2]), "r"(a[3]), "r"(b0), "r"(b1));
}
__device__ __forceinline__ void mma_f16(float c[4], const uint32_t a[4],
                                        uint32_t b0, uint32_t b1) {
    asm volatile("mma.sync.aligned.m16n8k16.row.col.f32.f16.f16.f32 "
        "{%0,%1,%2,%3}, {%4,%5,%6,%7}, {%8,%9}, {%0,%1,%2,%3};"
        : "+f"(c[0]), "+f"(c[1]), "+f"(c[2]), "+f"(c[3])
        : "r"(a[0]), "r"(a[1]), "r"(a[2]), "r"(a[3]), "r"(b0), "r"(b1));
}
__device__ __forceinline__ void cp16(uint32_t dst, const void* src) {
    asm volatile("cp.async.cg.shared.global [%0], [%1], 16;"
        :: "r"(dst), "l"(src) : "memory");
}
#define CP_COMMIT() asm volatile("cp.async.commit_group;" ::: "memory")
#define CP_WAIT0()  asm volatile("cp.async.wait_group 0;" ::: "memory")

#define SWZ128(o) ((o) ^ (((o) >> 3) & 0x70))
#define SWZ256(o) ((o) ^ (((o) >> 4) & 0x70))

__device__ __forceinline__ uint32_t bfu(__nv_bfloat16 h) {
    return (uint32_t)__bfloat16_as_ushort(h);
}
__device__ __forceinline__ void split8(const float* f, uint4& H, uint4& L) {
    uint32_t h[4], l[4];
    #pragma unroll
    for (int p = 0; p < 4; p++) {
        float x0 = f[2*p], x1 = f[2*p+1];
        __nv_bfloat16 h0 = __float2bfloat16(x0);
        __nv_bfloat16 h1 = __float2bfloat16(x1);
        h[p] = bfu(h0) | (bfu(h1) << 16);
        float r0 = x0 - __bfloat162float(h0);
        float r1 = x1 - __bfloat162float(h1);
        l[p] = bfu(__float2bfloat16(r0)) | (bfu(__float2bfloat16(r1)) << 16);
    }
    H = make_uint4(h[0], h[1], h[2], h[3]);
    L = make_uint4(l[0], l[1], l[2], l[3]);
}
__device__ __forceinline__ uint32_t h2u(__half2 h) {
    return *reinterpret_cast<uint32_t*>(&h);
}

__device__ __forceinline__ float score_fn(float qk, bool msk) {
    const float CLIPV = 1.0f - 1e-7f;
    qk = fminf(fmaxf(qk, -CLIPV), CLIPV);
    float gd = msk ? 10000.0f : acosf(qk);
    float t = 1.0f + gd;
    float t2 = t * t;
    return __fdividef(1.0f, t2 * t2 * t);
}

// ---------------------------------------------------------------------------
// Pass 0: pre-split Q,K -> global bf16 hi/lo planes
// ---------------------------------------------------------------------------
__global__ __launch_bounds__(256, 1)
void spop_pass0(const float* __restrict__ Q, const float* __restrict__ K)
{
    size_t t = (size_t)blockIdx.x * 256 + threadIdx.x;
    {
        float4 a = ((const float4*)Q)[t*2], b = ((const float4*)Q)[t*2+1];
        float f[8] = {a.x,a.y,a.z,a.w,b.x,b.y,b.z,b.w};
        uint4 H, L; split8(f, H, L);
        g_qh4[t] = H; g_ql4[t] = L;
    }
    {
        float4 a = ((const float4*)K)[t*2], b = ((const float4*)K)[t*2+1];
        float f[8] = {a.x,a.y,a.z,a.w,b.x,b.y,b.z,b.w};
        uint4 H, L; split8(f, H, L);
        g_kh4[t] = H; g_kl4[t] = L;
    }
}

// smem pass1
#define P1_KH 0
#define P1_KL 16384
#define P1_Q  32768           // two 32KB buffers (hi 16KB + lo 16KB each)
#define P1_RED 98304
#define P1_SMEM (98304 + 1024)

// ---------------------------------------------------------------------------
// Pass 1 (512 threads / 16 warps): qk = K·Q^T via HMMA bf16x2 (hh+lh+hl).
//   Each warp owns a 16(m) x 64(n) sub-tile -> 4 warps/SMSP hide latency.
// ---------------------------------------------------------------------------
__global__ __launch_bounds__(512, 1)
void spop_pass1_mma(const int* __restrict__ mask)
{
    extern __shared__ char sm[];
    const uint32_t sb = smem_u32(sm);

    const int bh = blockIdx.y;
    const int b  = bh / HHEADS;
    const int m0 = blockIdx.x * 128;
    const int tid = threadIdx.x;
    const int lane = tid & 31;
    const int wid  = tid >> 5;
    const int wm = wid & 7;        // m sixteenth (16 rows)
    const int wn = wid >> 3;       // n half (64 cols)
    const int g   = lane >> 2;
    const int tig = lane & 3;

    // ---- cp.async K planes + Q(0) planes (512 threads: 2 units each) ----
    {
        #pragma unroll
        for (int i = 0; i < 2; i++) {
            int gr = tid + 512 * i;
            int row = gr >> 3, u = gr & 7;
            size_t sbyte = ((size_t)(bh * NSEQ + m0 + row) * DDIM) * 2 + (size_t)u * 16;
            uint32_t doff = SWZ128((uint32_t)(row * 128 + u * 16));
            cp16(sb + P1_KH + doff, (const char*)g_kh4 + sbyte);
            cp16(sb + P1_KL + doff, (const char*)g_kl4 + sbyte);
        }
        #pragma unroll
        for (int i = 0; i < 2; i++) {
            int gr = tid + 512 * i;
            int row = gr >> 3, u = gr & 7;
            size_t sbyte = ((size_t)(bh * NSEQ + row) * DDIM) * 2 + (size_t)u * 16;
            uint32_t doff = SWZ128((uint32_t)(row * 128 + u * 16));
            cp16(sb + P1_Q + doff,         (const char*)g_qh4 + sbyte);
            cp16(sb + P1_Q + 16384 + doff, (const char*)g_ql4 + sbyte);
        }
        CP_COMMIT();
    }

    bool mskf[2];
    #pragma unroll
    for (int h = 0; h < 2; h++) {
        int mloc = wm * 16 + h * 8 + g;
        mskf[h] = (mask[b * NSEQ + m0 + mloc] == 0);
    }
    float rowacc[2] = {0.f, 0.f};

    const uint32_t a_row = (uint32_t)(wm * 16 + (lane & 15));
    const uint32_t a_k16 = (uint32_t)((lane >> 4) * 16);
    const uint32_t b_row = (uint32_t)(wn * 64 + ((lane >> 3) & 1) * 8 + (lane & 7));
    const uint32_t b_k16 = (uint32_t)((lane >> 4) * 16);

    for (int it = 0; it < NSEQ / 128; it++) {
        CP_WAIT0();
        __syncthreads();

        if (it < 15) {
            uint32_t qb = sb + P1_Q + (uint32_t)(((it + 1) & 1) * 32768);
            #pragma unroll
            for (int i = 0; i < 2; i++) {
                int gr = tid + 512 * i;
                int row = gr >> 3, u = gr & 7;
                size_t sbyte = ((size_t)(bh * NSEQ + (it + 1) * 128 + row) * DDIM) * 2
                               + (size_t)u * 16;
                uint32_t doff = SWZ128((uint32_t)(row * 128 + u * 16));
                cp16(qb + doff,         (const char*)g_qh4 + sbyte);
                cp16(qb + 16384 + doff, (const char*)g_ql4 + sbyte);
            }
            CP_COMMIT();
        }

        const uint32_t qHb = sb + P1_Q + (uint32_t)((it & 1) * 32768);
        const uint32_t qLb = qHb + 16384;
        const uint32_t kHb = sb + P1_KH;
        const uint32_t kLb = sb + P1_KL;

        float acc[8][4];
        #pragma unroll
        for (int tn = 0; tn < 8; tn++)
            #pragma unroll
            for (int c = 0; c < 4; c++) acc[tn][c] = 0.f;

        #pragma unroll
        for (int kc = 0; kc < 4; kc++) {
            uint32_t Ah[4], Al[4], Bq[4][4];
            const uint32_t kb = (uint32_t)(kc * 32) + a_k16;
            ldsm_x4(Ah, kHb + SWZ128(a_row * 128 + kb));
            #pragma unroll
            for (int p = 0; p < 4; p++)
                ldsm_x4(Bq[p], qHb + SWZ128((b_row + p*16) * 128 + (uint32_t)(kc*32) + b_k16));
            #pragma unroll
            for (int tn = 0; tn < 8; tn++)
                mma_bf16(acc[tn], Ah, Bq[tn>>1][(tn&1)], Bq[tn>>1][2 + (tn&1)]);
            ldsm_x4(Al, kLb + SWZ128(a_row * 128 + kb));
            #pragma unroll
            for (int tn = 0; tn < 8; tn++)
                mma_bf16(acc[tn], Al, Bq[tn>>1][(tn&1)], Bq[tn>>1][2 + (tn&1)]);
            #pragma unroll
            for (int p = 0; p < 4; p++)
                ldsm_x4(Bq[p], qLb + SWZ128((b_row + p*16) * 128 + (uint32_t)(kc*32) + b_k16));
            #pragma unroll
            for (int tn = 0; tn < 8; tn++)
                mma_bf16(acc[tn], Ah, Bq[tn>>1][(tn&1)], Bq[tn>>1][2 + (tn&1)]);
        }

        // ---- epilogue: transform -> fp16 plane + column sums ----
        const int n0 = it * 128;
        #pragma unroll
        for (int h = 0; h < 2; h++) {
            const int mloc = wm * 16 + h * 8 + g;
            const bool mk = mskf[h];
            size_t rowbase = ((size_t)bh * NSEQ + m0 + mloc) * NSEQ
                             + n0 + wn * 64 + 2 * tig;
            uint32_t* dF = (uint32_t*)g_sF4 + (rowbase >> 1);
            float racc = 0.f;
            #pragma unroll
            for (int tn = 0; tn < 8; tn++) {
                float s0 = score_fn(acc[tn][2*h],     mk);
                float s1 = score_fn(acc[tn][2*h + 1], mk);
                racc += s0 + s1;
                dF[tn * 4] = h2u(__floats2half2_rn(s0, s1));
            }
            rowacc[h] += racc;
        }
    }

    #pragma unroll
    for (int h = 0; h < 2; h++) {
        rowacc[h] += __shfl_xor_sync(0xffffffffu, rowacc[h], 1);
        rowacc[h] += __shfl_xor_sync(0xffffffffu, rowacc[h], 2);
    }
    float* red = (float*)(sm + P1_RED);
    __syncthreads();
    if (tig == 0) {
        #pragma unroll
        for (int h = 0; h < 2; h++) {
            int mloc = wm * 16 + h * 8 + g;
            red[wn * 128 + mloc] = rowacc[h];
        }
    }
    __syncthreads();
    if (tid < 128) {
        bool mk = (mask[b * NSEQ + m0 + tid] == 0);
        float nci = mk ? 0.0f : rsqrtf(red[tid] + red[128 + tid]);
        g_ncinv[bh * NSEQ + m0 + tid] = nci;
    }
}

// smem pass2: W double buffer (2x32KB) + V double buffer (2x18KB)
#define P2_V   65536
#define P2_VBUF 18432
#define P2_SMEM (65536 + 2 * 18432)   // 102400
#define VSTRIDE 144   // 72 halves per row

// ---------------------------------------------------------------------------
// Pass 2 (2 CTAs/SM): out[n,:] = (Σ_m s·(nci·V)) / (Σ_m s·nci); fp16 MMA.
//   V double-buffered in smem: conversion for it+1 overlaps MMA of it.
// ---------------------------------------------------------------------------
__global__ __launch_bounds__(256, 2)
void spop_pass2_mma(const float* __restrict__ V,
                    float*       __restrict__ out)
{
    extern __shared__ char sm[];
    const uint32_t sb = smem_u32(sm);

    const int bh = blockIdx.y;
    const int n0 = blockIdx.x * 128;
    const int tid = threadIdx.x;
    const int lane = tid & 31;
    const int wid  = tid >> 5;
    const int wrow = wid * 16;
    const int g = lane >> 2, tig = lane & 3;

    float acc[9][4];
    #pragma unroll
    for (int dt = 0; dt < 9; dt++)
        #pragma unroll
        for (int c = 0; c < 4; c++) acc[dt][c] = 0.f;

    const uint32_t a_min  = (uint32_t)((lane & 7) + ((lane >> 4) & 1) * 8);
    const uint32_t a_noff = (uint32_t)(((lane >> 3) & 1) * 8);
    const uint32_t b_kin  = (uint32_t)((lane & 7) + ((lane >> 3) & 1) * 8);
    const uint32_t b_doff = (uint32_t)((lane >> 4) * 8);
    const uint32_t b_kin2 = (uint32_t)(lane & 15);

    const int vr = tid >> 1, vhalf = tid & 1;

    // V tile convert (chunk mc) -> V buffer vbuf
    auto v_fill = [&](int mc, int vbuf) {
        const float nci = g_ncinv[bh * NSEQ + mc * 128 + vr];
        const float4* Vg = (const float4*)(V + ((size_t)bh * NSEQ + mc * 128 + vr) * DDIM
                                           + vhalf * 32);
        char* vb = sm + P2_V + vbuf * P2_VBUF;
        #pragma unroll
        for (int u = 0; u < 4; u++) {
            float4 a = Vg[2*u], c = Vg[2*u+1];
            uint32_t p0 = h2u(__floats2half2_rn(a.x * nci, a.y * nci));
            uint32_t p1 = h2u(__floats2half2_rn(a.z * nci, a.w * nci));
            uint32_t p2 = h2u(__floats2half2_rn(c.x * nci, c.y * nci));
            uint32_t p3 = h2u(__floats2half2_rn(c.z * nci, c.w * nci));
            *(uint4*)(vb + vr * VSTRIDE + vhalf * 64 + u * 16) =
                make_uint4(p0, p1, p2, p3);
        }
        if (vhalf == 1) {
            uint32_t nb = h2u(__floats2half2_rn(nci, 0.0f));
            *(uint4*)(vb + vr * VSTRIDE + 128) = make_uint4(nb, 0u, 0u, 0u);
        }
    };

    // prologue: cp.async W(0) + convert V(0)
    {
        const size_t cbase = ((size_t)bh * NSEQ) * NSEQ + n0;
        #pragma unroll
        for (int i = 0; i < 8; i++) {
            int gr = tid + 256 * i;
            int row = gr >> 4, u = gr & 15;
            size_t sbyte = (cbase + (size_t)row * NSEQ) * 2 + (size_t)u * 16;
            uint32_t doff = SWZ256((uint32_t)(row * 256 + u * 16));
            cp16(sb + doff, (const char*)g_sF4 + sbyte);
        }
        CP_COMMIT();
        v_fill(0, 0);
    }

    for (int it = 0; it < NSEQ / 128; it++) {
        CP_WAIT0();
        __syncthreads();

        if (it < 15) {
            // prefetch W(it+1) + convert V(it+1) into the other buffers
            uint32_t wb = sb + (uint32_t)(((it + 1) & 1) * 32768);
            const size_t cbase = ((size_t)bh * NSEQ + (it + 1) * 128) * NSEQ + n0;
            #pragma unroll
            for (int i = 0; i < 8; i++) {
                int gr = tid + 256 * i;
                int row = gr >> 4, u = gr & 15;
                size_t sbyte = (cbase + (size_t)row * NSEQ) * 2 + (size_t)u * 16;
                uint32_t doff = SWZ256((uint32_t)(row * 256 + u * 16));
                cp16(wb + doff, (const char*)g_sF4 + sbyte);
            }
            CP_COMMIT();
            v_fill(it + 1, (it + 1) & 1);
        }

        const uint32_t wB = sb + (uint32_t)((it & 1) * 32768);
        const uint32_t vB = sb + P2_V + (uint32_t)((it & 1) * P2_VBUF);

        #pragma unroll
        for (int kc = 0; kc < 8; kc++) {
            uint32_t Aw[4], Bv[4][4], Bv8[2];
            const uint32_t mbyte = ((uint32_t)(kc * 16) + a_min) * 256;
            const uint32_t nbyte = ((uint32_t)wrow + a_noff) * 2;
            ldsm_x4_t(Aw, wB + SWZ256(mbyte + nbyte));
            #pragma unroll
            for (int p = 0; p < 4; p++)
                ldsm_x4_t(Bv[p], vB + ((uint32_t)(kc*16) + b_kin) * VSTRIDE
                                + (uint32_t)(p * 32) + b_doff * 2);
            ldsm_x2_t(Bv8, vB + ((uint32_t)(kc*16) + b_kin2) * VSTRIDE + 128);
            #pragma unroll
            for (int dt = 0; dt < 8; dt++)
                mma_f16(acc[dt], Aw, Bv[dt>>1][(dt&1)*2], Bv[dt>>1][(dt&1)*2+1]);
            mma_f16(acc[8], Aw, Bv8[0], Bv8[1]);
        }
    }

    const int srcl = lane & ~3;
    float sum0 = __shfl_sync(0xffffffffu, acc[8][0], srcl);
    float sum1 = __shfl_sync(0xffffffffu, acc[8][2], srcl);
    float inv0 = __fdividef(1.0f, sum0);
    float inv1 = __fdividef(1.0f, sum1);

    const int ng0 = n0 + wrow + g;
    float* O0 = out + ((size_t)bh * NSEQ + ng0) * DDIM + 2 * tig;
    float* O1 = out + ((size_t)bh * NSEQ + ng0 + 8) * DDIM + 2 * tig;
    #pragma unroll
    for (int dt = 0; dt < 8; dt++) {
        *(float2*)(O0 + dt * 8) = make_float2(acc[dt][0] * inv0, acc[dt][1] * inv0);
        *(float2*)(O1 + dt * 8) = make_float2(acc[dt][2] * inv1, acc[dt][3] * inv1);
    }
}

// ---------------------------------------------------------------------------
extern "C" void kernel_launch(void* const* d_in, const int* in_sizes, int n_in,
                              void* d_out, int out_size)
{
    const float* Q    = (const float*)d_in[0];
    const float* K    = (const float*)d_in[1];
    const float* V    = (const float*)d_in[2];
    const int*   mask = (const int*)d_in[3];
    float*       out  = (float*)d_out;

    cudaFuncSetAttribute(spop_pass1_mma, cudaFuncAttributeMaxDynamicSharedMemorySize, P1_SMEM);
    cudaFuncSetAttribute(spop_pass2_mma, cudaFuncAttributeMaxDynamicSharedMemorySize, P2_SMEM);

    dim3 grid(NSEQ / 128, BHN);
    spop_pass0<<<(int)(QK_ELEMS / 8 / 256), 256>>>(Q, K);
    spop_pass1_mma<<<grid, 512, P1_SMEM>>>(mask);
    spop_pass2_mma<<<grid, 256, P2_SMEM>>>(V, out);
}

// round 8
// speedup vs baseline: 3.0660x; 1.2237x over previous
#include <cuda_runtime.h>
#include <cuda_bf16.h>
#include <cuda_fp16.h>
#include <math.h>
#include <cstdint>

#define NSEQ 2048
#define DDIM 64
#define HHEADS 8
#define BHN 16

#define QK_ELEMS ((size_t)BHN * NSEQ * DDIM)
#define S_ELEMS  ((size_t)BHN * NSEQ * NSEQ)

__device__ uint4 g_qh4[QK_ELEMS / 8], g_ql4[QK_ELEMS / 8];
__device__ uint4 g_kh4[QK_ELEMS / 8], g_kl4[QK_ELEMS / 8];
__device__ uint4 g_sF4[S_ELEMS / 8];          // fp16 scores [bh][m][n]
__device__ float g_ncinv[BHN * NSEQ];

// ---------------------------------------------------------------------------
__device__ __forceinline__ uint32_t smem_u32(const void* p) {
    uint32_t a;
    asm("{ .reg .u64 t; cvta.to.shared.u64 t, %1; cvt.u32.u64 %0, t; }"
        : "=r"(a) : "l"(p));
    return a;
}
__device__ __forceinline__ void ldsm_x4(uint32_t r[4], uint32_t a) {
    asm volatile("ldmatrix.sync.aligned.m8n8.x4.shared.b16 {%0,%1,%2,%3}, [%4];"
        : "=r"(r[0]), "=r"(r[1]), "=r"(r[2]), "=r"(r[3]) : "r"(a));
}
__device__ __forceinline__ void ldsm_x4_t(uint32_t r[4], uint32_t a) {
    asm volatile("ldmatrix.sync.aligned.m8n8.x4.trans.shared.b16 {%0,%1,%2,%3}, [%4];"
        : "=r"(r[0]), "=r"(r[1]), "=r"(r[2]), "=r"(r[3]) : "r"(a));
}
__device__ __forceinline__ void ldsm_x2_t(uint32_t r[2], uint32_t a) {
    asm volatile("ldmatrix.sync.aligned.m8n8.x2.trans.shared.b16 {%0,%1}, [%2];"
        : "=r"(r[0]), "=r"(r[1]) : "r"(a));
}
__device__ __forceinline__ void mma_bf16(float c[4], const uint32_t a[4],
                                         uint32_t b0, uint32_t b1) {
    asm volatile("mma.sync.aligned.m16n8k16.row.col.f32.bf16.bf16.f32 "
        "{%0,%1,%2,%3}, {%4,%5,%6,%7}, {%8,%9}, {%0,%1,%2,%3};"
        : "+f"(c[0]), "+f"(c[1]), "+f"(c[2]), "+f"(c[3])
        : "r"(a[0]), "r"(a[1]), "r"(a[2]), "r"(a[3]), "r"(b0), "r"(b1));
}
__device__ __forceinline__ void mma_f16(float c[4], const uint32_t a[4],
                                        uint32_t b0, uint32_t b1) {
    asm volatile("mma.sync.aligned.m16n8k16.row.col.f32.f16.f16.f32 "
        "{%0,%1,%2,%3}, {%4,%5,%6,%7}, {%8,%9}, {%0,%1,%2,%3};"
        : "+f"(c[0]), "+f"(c[1]), "+f"(c[2]), "+f"(c[3])
        : "r"(a[0]), "r"(a[1]), "r"(a[2]), "r"(a[3]), "r"(b0), "r"(b1));
}
__device__ __forceinline__ void cp16(uint32_t dst, const void* src) {
    asm volatile("cp.async.cg.shared.global [%0], [%1], 16;"
        :: "r"(dst), "l"(src) : "memory");
}
#define CP_COMMIT() asm volatile("cp.async.commit_group;" ::: "memory")
#define CP_WAIT0()  asm volatile("cp.async.wait_group 0;" ::: "memory")

#define SWZ128(o) ((o) ^ (((o) >> 3) & 0x70))
#define SWZ256(o) ((o) ^ (((o) >> 4) & 0x70))

__device__ __forceinline__ uint32_t bfu(__nv_bfloat16 h) {
    return (uint32_t)__bfloat16_as_ushort(h);
}
__device__ __forceinline__ void split8(const float* f, uint4& H, uint4& L) {
    uint32_t h[4], l[4];
    #pragma unroll
    for (int p = 0; p < 4; p++) {
        float x0 = f[2*p], x1 = f[2*p+1];
        __nv_bfloat16 h0 = __float2bfloat16(x0);
        __nv_bfloat16 h1 = __float2bfloat16(x1);
        h[p] = bfu(h0) | (bfu(h1) << 16);
        float r0 = x0 - __bfloat162float(h0);
        float r1 = x1 - __bfloat162float(h1);
        l[p] = bfu(__float2bfloat16(r0)) | (bfu(__float2bfloat16(r1)) << 16);
    }
    H = make_uint4(h[0], h[1], h[2], h[3]);
    L = make_uint4(l[0], l[1], l[2], l[3]);
}
__device__ __forceinline__ uint32_t h2u(__half2 h) {
    return *reinterpret_cast<uint32_t*>(&h);
}
__device__ __forceinline__ float sqrt_approx(float x) {
    float r; asm("sqrt.approx.f32 %0, %1;" : "=f"(r) : "f"(x)); return r;
}

// Fast score: (1 + acos(clip(qk)))^-5 with A&S 4.4.47 polynomial acos
// (abs err ~1e-7; endpoint-correct: P7(1)=sqrt(2) matches acos(1-e)=sqrt(2e))
__device__ __forceinline__ float score_fn(float qk, bool msk) {
    const float CLIPV = 1.0f - 1e-7f;
    float x = fminf(fmaxf(qk, -CLIPV), CLIPV);
    float y = fabsf(x);
    float p = fmaf(-0.0012624911f, y, 0.0066700901f);
    p = fmaf(p, y, -0.0170881256f);
    p = fmaf(p, y,  0.0308918810f);
    p = fmaf(p, y, -0.0501743046f);
    p = fmaf(p, y,  0.0889789874f);
    p = fmaf(p, y, -0.2145988016f);
    p = fmaf(p, y,  1.5707963268f);
    float r = sqrt_approx(1.0f - y) * p;
    float g = (x < 0.0f) ? (3.14159265358979f - r) : r;
    g = msk ? 10000.0f : g;
    float t = 1.0f + g;
    float t2 = t * t;
    return __fdividef(1.0f, t2 * t2 * t);
}

// ---------------------------------------------------------------------------
// Pass 0: pre-split Q,K -> global bf16 hi/lo planes
// ---------------------------------------------------------------------------
__global__ __launch_bounds__(256, 1)
void spop_pass0(const float* __restrict__ Q, const float* __restrict__ K)
{
    size_t t = (size_t)blockIdx.x * 256 + threadIdx.x;
    {
        float4 a = ((const float4*)Q)[t*2], b = ((const float4*)Q)[t*2+1];
        float f[8] = {a.x,a.y,a.z,a.w,b.x,b.y,b.z,b.w};
        uint4 H, L; split8(f, H, L);
        g_qh4[t] = H; g_ql4[t] = L;
    }
    {
        float4 a = ((const float4*)K)[t*2], b = ((const float4*)K)[t*2+1];
        float f[8] = {a.x,a.y,a.z,a.w,b.x,b.y,b.z,b.w};
        uint4 H, L; split8(f, H, L);
        g_kh4[t] = H; g_kl4[t] = L;
    }
}

// smem pass1
#define P1_KH 0
#define P1_KL 16384
#define P1_Q  32768
#define P1_RED 98304
#define P1_SMEM (98304 + 1024)

// ---------------------------------------------------------------------------
// Pass 1 (512 threads / 16 warps): qk = K·Q^T via HMMA bf16x2 (hh+lh+hl).
// ---------------------------------------------------------------------------
__global__ __launch_bounds__(512, 1)
void spop_pass1_mma(const int* __restrict__ mask)
{
    extern __shared__ char sm[];
    const uint32_t sb = smem_u32(sm);

    const int bh = blockIdx.y;
    const int b  = bh / HHEADS;
    const int m0 = blockIdx.x * 128;
    const int tid = threadIdx.x;
    const int lane = tid & 31;
    const int wid  = tid >> 5;
    const int wm = wid & 7;
    const int wn = wid >> 3;
    const int g   = lane >> 2;
    const int tig = lane & 3;

    {
        #pragma unroll
        for (int i = 0; i < 2; i++) {
            int gr = tid + 512 * i;
            int row = gr >> 3, u = gr & 7;
            size_t sbyte = ((size_t)(bh * NSEQ + m0 + row) * DDIM) * 2 + (size_t)u * 16;
            uint32_t doff = SWZ128((uint32_t)(row * 128 + u * 16));
            cp16(sb + P1_KH + doff, (const char*)g_kh4 + sbyte);
            cp16(sb + P1_KL + doff, (const char*)g_kl4 + sbyte);
        }
        #pragma unroll
        for (int i = 0; i < 2; i++) {
            int gr = tid + 512 * i;
            int row = gr >> 3, u = gr & 7;
            size_t sbyte = ((size_t)(bh * NSEQ + row) * DDIM) * 2 + (size_t)u * 16;
            uint32_t doff = SWZ128((uint32_t)(row * 128 + u * 16));
            cp16(sb + P1_Q + doff,         (const char*)g_qh4 + sbyte);
            cp16(sb + P1_Q + 16384 + doff, (const char*)g_ql4 + sbyte);
        }
        CP_COMMIT();
    }

    bool mskf[2];
    #pragma unroll
    for (int h = 0; h < 2; h++) {
        int mloc = wm * 16 + h * 8 + g;
        mskf[h] = (mask[b * NSEQ + m0 + mloc] == 0);
    }
    float rowacc[2] = {0.f, 0.f};

    const uint32_t a_row = (uint32_t)(wm * 16 + (lane & 15));
    const uint32_t a_k16 = (uint32_t)((lane >> 4) * 16);
    const uint32_t b_row = (uint32_t)(wn * 64 + ((lane >> 3) & 1) * 8 + (lane & 7));
    const uint32_t b_k16 = (uint32_t)((lane >> 4) * 16);

    for (int it = 0; it < NSEQ / 128; it++) {
        CP_WAIT0();
        __syncthreads();

        if (it < 15) {
            uint32_t qb = sb + P1_Q + (uint32_t)(((it + 1) & 1) * 32768);
            #pragma unroll
            for (int i = 0; i < 2; i++) {
                int gr = tid + 512 * i;
                int row = gr >> 3, u = gr & 7;
                size_t sbyte = ((size_t)(bh * NSEQ + (it + 1) * 128 + row) * DDIM) * 2
                               + (size_t)u * 16;
                uint32_t doff = SWZ128((uint32_t)(row * 128 + u * 16));
                cp16(qb + doff,         (const char*)g_qh4 + sbyte);
                cp16(qb + 16384 + doff, (const char*)g_ql4 + sbyte);
            }
            CP_COMMIT();
        }

        const uint32_t qHb = sb + P1_Q + (uint32_t)((it & 1) * 32768);
        const uint32_t qLb = qHb + 16384;
        const uint32_t kHb = sb + P1_KH;
        const uint32_t kLb = sb + P1_KL;

        float acc[8][4];
        #pragma unroll
        for (int tn = 0; tn < 8; tn++)
            #pragma unroll
            for (int c = 0; c < 4; c++) acc[tn][c] = 0.f;

        #pragma unroll
        for (int kc = 0; kc < 4; kc++) {
            uint32_t Ah[4], Al[4], Bq[4][4];
            const uint32_t kb = (uint32_t)(kc * 32) + a_k16;
            ldsm_x4(Ah, kHb + SWZ128(a_row * 128 + kb));
            #pragma unroll
            for (int p = 0; p < 4; p++)
                ldsm_x4(Bq[p], qHb + SWZ128((b_row + p*16) * 128 + (uint32_t)(kc*32) + b_k16));
            #pragma unroll
            for (int tn = 0; tn < 8; tn++)
                mma_bf16(acc[tn], Ah, Bq[tn>>1][(tn&1)], Bq[tn>>1][2 + (tn&1)]);
            ldsm_x4(Al, kLb + SWZ128(a_row * 128 + kb));
            #pragma unroll
            for (int tn = 0; tn < 8; tn++)
                mma_bf16(acc[tn], Al, Bq[tn>>1][(tn&1)], Bq[tn>>1][2 + (tn&1)]);
            #pragma unroll
            for (int p = 0; p < 4; p++)
                ldsm_x4(Bq[p], qLb + SWZ128((b_row + p*16) * 128 + (uint32_t)(kc*32) + b_k16));
            #pragma unroll
            for (int tn = 0; tn < 8; tn++)
                mma_bf16(acc[tn], Ah, Bq[tn>>1][(tn&1)], Bq[tn>>1][2 + (tn&1)]);
        }

        // ---- epilogue: transform -> fp16 plane + column sums ----
        const int n0 = it * 128;
        #pragma unroll
        for (int h = 0; h < 2; h++) {
            const int mloc = wm * 16 + h * 8 + g;
            const bool mk = mskf[h];
            size_t rowbase = ((size_t)bh * NSEQ + m0 + mloc) * NSEQ
                             + n0 + wn * 64 + 2 * tig;
            uint32_t* dF = (uint32_t*)g_sF4 + (rowbase >> 1);
            float racc = 0.f;
            #pragma unroll
            for (int tn = 0; tn < 8; tn++) {
                float s0 = score_fn(acc[tn][2*h],     mk);
                float s1 = score_fn(acc[tn][2*h + 1], mk);
                racc += s0 + s1;
                dF[tn * 4] = h2u(__floats2half2_rn(s0, s1));
            }
            rowacc[h] += racc;
        }
    }

    #pragma unroll
    for (int h = 0; h < 2; h++) {
        rowacc[h] += __shfl_xor_sync(0xffffffffu, rowacc[h], 1);
        rowacc[h] += __shfl_xor_sync(0xffffffffu, rowacc[h], 2);
    }
    float* red = (float*)(sm + P1_RED);
    __syncthreads();
    if (tig == 0) {
        #pragma unroll
        for (int h = 0; h < 2; h++) {
            int mloc = wm * 16 + h * 8 + g;
            red[wn * 128 + mloc] = rowacc[h];
        }
    }
    __syncthreads();
    if (tid < 128) {
        bool mk = (mask[b * NSEQ + m0 + tid] == 0);
        float nci = mk ? 0.0f : rsqrtf(red[tid] + red[128 + tid]);
        g_ncinv[bh * NSEQ + m0 + tid] = nci;
    }
}

// smem pass2: W double buffer (2x32KB) + V double buffer (2x18KB)
#define P2_V   65536
#define P2_VBUF 18432
#define P2_SMEM (65536 + 2 * 18432)
#define VSTRIDE 144

// ---------------------------------------------------------------------------
// Pass 2 (2 CTAs/SM): out[n,:] = (Σ_m s·(nci·V)) / (Σ_m s·nci); fp16 MMA.
// ---------------------------------------------------------------------------
__global__ __launch_bounds__(256, 2)
void spop_pass2_mma(const float* __restrict__ V,
                    float*       __restrict__ out)
{
    extern __shared__ char sm[];
    const uint32_t sb = smem_u32(sm);

    const int bh = blockIdx.y;
    const int n0 = blockIdx.x * 128;
    const int tid = threadIdx.x;
    const int lane = tid & 31;
    const int wid  = tid >> 5;
    const int wrow = wid * 16;
    const int g = lane >> 2, tig = lane & 3;

    float acc[9][4];
    #pragma unroll
    for (int dt = 0; dt < 9; dt++)
        #pragma unroll
        for (int c = 0; c < 4; c++) acc[dt][c] = 0.f;

    const uint32_t a_min  = (uint32_t)((lane & 7) + ((lane >> 4) & 1) * 8);
    const uint32_t a_noff = (uint32_t)(((lane >> 3) & 1) * 8);
    const uint32_t b_kin  = (uint32_t)((lane & 7) + ((lane >> 3) & 1) * 8);
    const uint32_t b_doff = (uint32_t)((lane >> 4) * 8);
    const uint32_t b_kin2 = (uint32_t)(lane & 15);

    const int vr = tid >> 1, vhalf = tid & 1;

    auto v_fill = [&](int mc, int vbuf) {
        const float nci = g_ncinv[bh * NSEQ + mc * 128 + vr];
        const float4* Vg = (const float4*)(V + ((size_t)bh * NSEQ + mc * 128 + vr) * DDIM
                                           + vhalf * 32);
        char* vb = sm + P2_V + vbuf * P2_VBUF;
        #pragma unroll
        for (int u = 0; u < 4; u++) {
            float4 a = Vg[2*u], c = Vg[2*u+1];
            uint32_t p0 = h2u(__floats2half2_rn(a.x * nci, a.y * nci));
            uint32_t p1 = h2u(__floats2half2_rn(a.z * nci, a.w * nci));
            uint32_t p2 = h2u(__floats2half2_rn(c.x * nci, c.y * nci));
            uint32_t p3 = h2u(__floats2half2_rn(c.z * nci, c.w * nci));
            *(uint4*)(vb + vr * VSTRIDE + vhalf * 64 + u * 16) =
                make_uint4(p0, p1, p2, p3);
        }
        if (vhalf == 1) {
            uint32_t nb = h2u(__floats2half2_rn(nci, 0.0f));
            *(uint4*)(vb + vr * VSTRIDE + 128) = make_uint4(nb, 0u, 0u, 0u);
        }
    };

    {
        const size_t cbase = ((size_t)bh * NSEQ) * NSEQ + n0;
        #pragma unroll
        for (int i = 0; i < 8; i++) {
            int gr = tid + 256 * i;
            int row = gr >> 4, u = gr & 15;
            size_t sbyte = (cbase + (size_t)row * NSEQ) * 2 + (size_t)u * 16;
            uint32_t doff = SWZ256((uint32_t)(row * 256 + u * 16));
            cp16(sb + doff, (const char*)g_sF4 + sbyte);
        }
        CP_COMMIT();
        v_fill(0, 0);
    }

    for (int it = 0; it < NSEQ / 128; it++) {
        CP_WAIT0();
        __syncthreads();

        if (it < 15) {
            uint32_t wb = sb + (uint32_t)(((it + 1) & 1) * 32768);
            const size_t cbase = ((size_t)bh * NSEQ + (it + 1) * 128) * NSEQ + n0;
            #pragma unroll
            for (int i = 0; i < 8; i++) {
                int gr = tid + 256 * i;
                int row = gr >> 4, u = gr & 15;
                size_t sbyte = (cbase + (size_t)row * NSEQ) * 2 + (size_t)u * 16;
                uint32_t doff = SWZ256((uint32_t)(row * 256 + u * 16));
                cp16(wb + doff, (const char*)g_sF4 + sbyte);
            }
            CP_COMMIT();
            v_fill(it + 1, (it + 1) & 1);
        }

        const uint32_t wB = sb + (uint32_t)((it & 1) * 32768);
        const uint32_t vB = sb + P2_V + (uint32_t)((it & 1) * P2_VBUF);

        #pragma unroll
        for (int kc = 0; kc < 8; kc++) {
            uint32_t Aw[4], Bv[4][4], Bv8[2];
            const uint32_t mbyte = ((uint32_t)(kc * 16) + a_min) * 256;
            const uint32_t nbyte = ((uint32_t)wrow + a_noff) * 2;
            ldsm_x4_t(Aw, wB + SWZ256(mbyte + nbyte));
            #pragma unroll
            for (int p = 0; p < 4; p++)
                ldsm_x4_t(Bv[p], vB + ((uint32_t)(kc*16) + b_kin) * VSTRIDE
                                + (uint32_t)(p * 32) + b_doff * 2);
            ldsm_x2_t(Bv8, vB + ((uint32_t)(kc*16) + b_kin2) * VSTRIDE + 128);
            #pragma unroll
            for (int dt = 0; dt < 8; dt++)
                mma_f16(acc[dt], Aw, Bv[dt>>1][(dt&1)*2], Bv[dt>>1][(dt&1)*2+1]);
            mma_f16(acc[8], Aw, Bv8[0], Bv8[1]);
        }
    }

    const int srcl = lane & ~3;
    float sum0 = __shfl_sync(0xffffffffu, acc[8][0], srcl);
    float sum1 = __shfl_sync(0xffffffffu, acc[8][2], srcl);
    float inv0 = __fdividef(1.0f, sum0);
    float inv1 = __fdividef(1.0f, sum1);

    const int ng0 = n0 + wrow + g;
    float* O0 = out + ((size_t)bh * NSEQ + ng0) * DDIM + 2 * tig;
    float* O1 = out + ((size_t)bh * NSEQ + ng0 + 8) * DDIM + 2 * tig;
    #pragma unroll
    for (int dt = 0; dt < 8; dt++) {
        *(float2*)(O0 + dt * 8) = make_float2(acc[dt][0] * inv0, acc[dt][1] * inv0);
        *(float2*)(O1 + dt * 8) = make_float2(acc[dt][2] * inv1, acc[dt][3] * inv1);
    }
}

// ---------------------------------------------------------------------------
extern "C" void kernel_launch(void* const* d_in, const int* in_sizes, int n_in,
                              void* d_out, int out_size)
{
    const float* Q    = (const float*)d_in[0];
    const float* K    = (const float*)d_in[1];
    const float* V    = (const float*)d_in[2];
    const int*   mask = (const int*)d_in[3];
    float*       out  = (float*)d_out;

    cudaFuncSetAttribute(spop_pass1_mma, cudaFuncAttributeMaxDynamicSharedMemorySize, P1_SMEM);
    cudaFuncSetAttribute(spop_pass2_mma, cudaFuncAttributeMaxDynamicSharedMemorySize, P2_SMEM);

    dim3 grid(NSEQ / 128, BHN);
    spop_pass0<<<(int)(QK_ELEMS / 8 / 256), 256>>>(Q, K);
    spop_pass1_mma<<<grid, 512, P1_SMEM>>>(mask);
    spop_pass2_mma<<<grid, 256, P2_SMEM>>>(V, out);
}